// round 12
// baseline (speedup 1.0000x reference)
#include <cuda_runtime.h>
#include <cuda_fp16.h>
#include <math.h>
#include <stdint.h>

// ---------------------------------------------------------------------------
// Problem constants
// ---------------------------------------------------------------------------
#define MB   4
#define SS   2048
#define DD   256
#define HH   8
#define KDD  256
#define FFD  512
#define MTOK (MB * SS)        // 8192
#define HKD  (HH * KDD)       // 2048
#define BH   (MB * HH)        // 32
#define QKVN (3 * HKD)        // 6144
// 1/sqrt(KD) * log2(e)  — folded into Wq/bq so softmax runs in base 2
#define QSCL 0.0901684361f

// ---------------------------------------------------------------------------
// Static scratch (device .bss — no runtime allocation)
// ---------------------------------------------------------------------------
__device__ __align__(256) __half g_qkv16[(long long)MTOK * QKVN];   // [tok][q|k|v]
__device__ __align__(256) __half g_vt16 [(long long)BH * KDD * SS]; // [bh,e,s]
__device__ __align__(256) __half g_at16 [(long long)MTOK * HKD];    // [b,s,h,e]
__device__ float g_ao[(long long)MTOK * DD];
__device__ float g_z [(long long)MTOK * DD];
__device__ __align__(256) __half g_z16 [(long long)MTOK * DD];
__device__ __align__(256) __half g_h16 [(long long)MTOK * FFD];
__device__ float g_f [(long long)MTOK * DD];
// pre-converted / pre-transposed inputs
__device__ __align__(256) __half g_x16  [(long long)MTOK * DD];
__device__ __align__(256) __half g_wqkv [(long long)QKVN * DD];     // [6144,256]
__device__ float                 g_bqkv [QKVN];
__device__ __align__(256) __half g_wo16[(long long)DD * HKD];
__device__ __align__(256) __half g_w116[(long long)FFD * DD];
__device__ __align__(256) __half g_w216[(long long)DD * FFD];

// ---------------------------------------------------------------------------
// PTX helpers
// ---------------------------------------------------------------------------
#define CP_ASYNC16(saddr, gptr) \
    asm volatile("cp.async.cg.shared.global [%0], [%1], 16;" :: "r"(saddr), "l"(gptr))
#define CP_COMMIT()  asm volatile("cp.async.commit_group;" ::: "memory")
#define CP_WAIT_1()  asm volatile("cp.async.wait_group 1;" ::: "memory")
#define CP_WAIT_0()  asm volatile("cp.async.wait_group 0;" ::: "memory")

__device__ __forceinline__ uint32_t smem_u32(const void* p) {
    uint32_t a;
    asm("{ .reg .u64 t; cvta.to.shared.u64 t, %1; cvt.u32.u64 %0, t; }" : "=r"(a) : "l"(p));
    return a;
}

__device__ __forceinline__ void mma_f16(
    float& c0, float& c1, float& c2, float& c3,
    uint32_t a0, uint32_t a1, uint32_t a2, uint32_t a3,
    uint32_t b0, uint32_t b1)
{
    asm volatile(
        "mma.sync.aligned.m16n8k16.row.col.f32.f16.f16.f32 "
        "{%0,%1,%2,%3}, {%4,%5,%6,%7}, {%8,%9}, {%0,%1,%2,%3};"
        : "+f"(c0), "+f"(c1), "+f"(c2), "+f"(c3)
        : "r"(a0), "r"(a1), "r"(a2), "r"(a3), "r"(b0), "r"(b1));
}

#define LDSM_X4(r0, r1, r2, r3, addr) \
    asm volatile("ldmatrix.sync.aligned.m8n8.x4.shared.b16 {%0,%1,%2,%3}, [%4];" \
                 : "=r"(r0), "=r"(r1), "=r"(r2), "=r"(r3) : "r"(addr))

__device__ __forceinline__ uint32_t packh2(float lo, float hi) {
    uint32_t u;
    asm("cvt.rn.f16x2.f32 %0, %1, %2;" : "=r"(u) : "f"(hi), "f"(lo));
    return u;
}

__device__ __forceinline__ float ex2(float x) {
    float y;
    asm("ex2.approx.f32 %0, %1;" : "=f"(y) : "f"(x));
    return y;
}

// ---------------------------------------------------------------------------
// TN fp16 tensor-core GEMM (proven bit-correct; unchanged)
// ---------------------------------------------------------------------------
#define BKH 64
#define ROWW 36
#define OPW  (128 * ROWW)
#define STW  (2 * OPW)
#define HG_SMEM (2 * STW * 4)       // 73728 bytes

__global__ void __launch_bounds__(256)
hgemm(const __half* __restrict__ A, const __half* __restrict__ B,
      void* __restrict__ Cv, const float* __restrict__ bias,
      int K, int lda, int ldb, int ldc,
      int batch_div,
      long long sAo, long long sAi,
      long long sBo, long long sBi,
      long long sCo, long long sCi,
      float alpha, int relu, int outhalf)
{
    extern __shared__ uint32_t smw[];
    const uint32_t sbase = smem_u32(smw);

    const int z  = blockIdx.z;
    const int zo = z / batch_div;
    const int zi = z - zo * batch_div;
    A += zo * sAo + zi * sAi;
    B += zo * sBo + zi * sBi;

    const int tid  = threadIdx.x;
    const int lane = tid & 31;
    const int wrp  = tid >> 5;
    const int m0   = blockIdx.y * 128;
    const int n0   = blockIdx.x * 128;

    const int wm = (wrp & 1) * 64;
    const int wn = (wrp >> 1) * 32;
    const int g  = lane >> 2;
    const int tg = lane & 3;

    const __half* Ab = A + (long long)m0 * lda;
    const __half* Bb = B + (long long)n0 * ldb;

    float acc[4][4][4];
#pragma unroll
    for (int mi = 0; mi < 4; mi++)
#pragma unroll
        for (int ni = 0; ni < 4; ni++)
#pragma unroll
            for (int r = 0; r < 4; r++) acc[mi][ni][r] = 0.f;

    const int l15 = lane & 15;
    const int l7  = lane & 7;
    uint32_t aAddr[4], bAddr[2];
#pragma unroll
    for (int mi = 0; mi < 4; mi++)
        aAddr[mi] = sbase + ((wm + mi * 16 + l15) * ROWW + (lane >> 4) * 4) * 4;
#pragma unroll
    for (int p = 0; p < 2; p++)
        bAddr[p] = sbase + OPW * 4 +
                   ((wn + p * 16 + (lane >> 4) * 8 + l7) * ROWW +
                    ((lane >> 3) & 1) * 4) * 4;

    const int lrow = tid >> 3;
    const int lk8  = tid & 7;

    auto issue = [&](int st, int k0) {
        const uint32_t s0 = sbase + (st * STW) * 4;
#pragma unroll
        for (int i = 0; i < 4; i++) {
            const int row = lrow + i * 32;
            const uint32_t off = (row * ROWW + lk8 * 4) * 4;
            CP_ASYNC16(s0 + off,           Ab + (long long)row * lda + k0 + lk8 * 8);
            CP_ASYNC16(s0 + OPW * 4 + off, Bb + (long long)row * ldb + k0 + lk8 * 8);
        }
        CP_COMMIT();
    };

    const int T = K / BKH;
    issue(0, 0);

    for (int it = 0; it < T; it++) {
        const int st = it & 1;
        if (it + 1 < T) {
            issue(st ^ 1, (it + 1) * BKH);
            CP_WAIT_1();
        } else {
            CP_WAIT_0();
        }
        __syncthreads();

        const uint32_t sOff = (uint32_t)(st * STW) * 4;

#pragma unroll
        for (int ks = 0; ks < 4; ks++) {
            const uint32_t ko = sOff + ks * 32;
            uint32_t a[4][4];
#pragma unroll
            for (int mi = 0; mi < 4; mi++)
                LDSM_X4(a[mi][0], a[mi][1], a[mi][2], a[mi][3], aAddr[mi] + ko);
            uint32_t b[4][2];
#pragma unroll
            for (int p = 0; p < 2; p++)
                LDSM_X4(b[2 * p][0], b[2 * p][1], b[2 * p + 1][0], b[2 * p + 1][1],
                        bAddr[p] + ko);
#pragma unroll
            for (int mi = 0; mi < 4; mi++)
#pragma unroll
                for (int ni = 0; ni < 4; ni++)
                    mma_f16(acc[mi][ni][0], acc[mi][ni][1],
                            acc[mi][ni][2], acc[mi][ni][3],
                            a[mi][0], a[mi][1], a[mi][2], a[mi][3],
                            b[ni][0], b[ni][1]);
        }
        __syncthreads();
    }

    float*  Cf = (float*)Cv  + zo * sCo + zi * sCi;
    __half* Ch = (__half*)Cv + zo * sCo + zi * sCi;
#pragma unroll
    for (int mi = 0; mi < 4; mi++) {
        const int r0 = m0 + wm + mi * 16 + g;
#pragma unroll
        for (int ni = 0; ni < 4; ni++) {
            const int col = n0 + wn + ni * 8 + tg * 2;
            float v0 = acc[mi][ni][0], v1 = acc[mi][ni][1];
            float v2 = acc[mi][ni][2], v3 = acc[mi][ni][3];
            if (bias) {
                const float b0 = bias[col], b1 = bias[col + 1];
                v0 += b0; v1 += b1; v2 += b0; v3 += b1;
            }
            v0 *= alpha; v1 *= alpha; v2 *= alpha; v3 *= alpha;
            if (relu) {
                v0 = fmaxf(v0, 0.f); v1 = fmaxf(v1, 0.f);
                v2 = fmaxf(v2, 0.f); v3 = fmaxf(v3, 0.f);
            }
            if (outhalf) {
                *(__half2*)(Ch + (long long)r0 * ldc + col) =
                    __floats2half2_rn(v0, v1);
                *(__half2*)(Ch + (long long)(r0 + 8) * ldc + col) =
                    __floats2half2_rn(v2, v3);
            } else {
                *(float2*)(Cf + (long long)r0 * ldc + col)       = make_float2(v0, v1);
                *(float2*)(Cf + (long long)(r0 + 8) * ldc + col) = make_float2(v2, v3);
            }
        }
    }
}

// ---------------------------------------------------------------------------
// Fused flash attention (base-2 softmax, rescale skip).
// qkv: [tok][6144] fp16, segments q|k|v; q pre-scaled by 1/sqrt(KD)*log2e.
// vt: [bh,e,s]. o: [b,s,h,e].
// ---------------------------------------------------------------------------
#define QROWB 528
#define VROWB 144
#define QBYT  (128 * QROWB)
#define KBYT  (64 * QROWB)
#define VBYT  (256 * VROWB)
#define STBYT (KBYT + VBYT)
#define FA_SMEM (QBYT + 2 * STBYT)   // 208896

__global__ void __launch_bounds__(256, 1)
fattn(const __half* __restrict__ qkv, const __half* __restrict__ vt,
      __half* __restrict__ o)
{
    extern __shared__ char fsm[];
    const uint32_t sb = smem_u32(fsm);

    const int tid = threadIdx.x, lane = tid & 31, w = tid >> 5;
    const int g = lane >> 2, tg = lane & 3;
    const int l15 = lane & 15, l7 = lane & 7;
    const int qt = blockIdx.x, bh = blockIdx.y;
    const int b = bh >> 3, h = bh & 7;
    const long long tokQ = (long long)b * SS + qt * 128;
    const __half* qp = qkv + h * KDD;                 // q segment
    const __half* kp = qkv + HKD + h * KDD;           // k segment

    // ---- load Q tile (128 x 256 halves), once ----
#pragma unroll
    for (int i = 0; i < 16; i++) {
        const int c = tid + i * 256, row = c >> 5, col = c & 31;
        CP_ASYNC16(sb + row * QROWB + col * 16,
                   qp + (tokQ + row) * QKVN + col * 8);
    }
    CP_COMMIT();

    auto loadKV = [&](int st, int kt) {
        const uint32_t kb = sb + QBYT + st * STBYT;
        const uint32_t vb = kb + KBYT;
#pragma unroll
        for (int i = 0; i < 8; i++) {
            const int c = tid + i * 256, row = c >> 5, col = c & 31;
            CP_ASYNC16(kb + row * QROWB + col * 16,
                       kp + ((long long)b * SS + kt * 64 + row) * QKVN + col * 8);
        }
#pragma unroll
        for (int i = 0; i < 8; i++) {
            const int c = tid + i * 256, d = c >> 3, kc = c & 7;
            CP_ASYNC16(vb + d * VROWB + kc * 16,
                       vt + ((long long)bh * KDD + d) * SS + kt * 64 + kc * 8);
        }
        CP_COMMIT();
    };

    loadKV(0, 0);

    float acc[32][4];
#pragma unroll
    for (int nd = 0; nd < 32; nd++)
#pragma unroll
        for (int r = 0; r < 4; r++) acc[nd][r] = 0.f;
    float m0 = -1e30f, m1 = -1e30f, l0 = 0.f, l1 = 0.f;

    const uint32_t qa = sb + (w * 16 + l15) * QROWB + (lane >> 4) * 16;

    for (int kt = 0; kt < 32; kt++) {
        const int st = kt & 1;
        if (kt + 1 < 32) { loadKV(st ^ 1, kt + 1); CP_WAIT_1(); }
        else             { CP_WAIT_0(); }
        __syncthreads();

        const uint32_t kb = sb + QBYT + st * STBYT;
        const uint32_t vb = kb + KBYT;
        const uint32_t ka = kb + ((lane >> 4) * 8 + l7) * QROWB + ((lane >> 3) & 1) * 16;
        const uint32_t va = vb + ((lane >> 4) * 8 + l7) * VROWB + ((lane >> 3) & 1) * 16;

        // ---- S = Qw (16 x 256) @ Ktile^T (64 x 256), base-2 scaled ----
        float s[8][4];
#pragma unroll
        for (int ni = 0; ni < 8; ni++)
#pragma unroll
            for (int r = 0; r < 4; r++) s[ni][r] = 0.f;

#pragma unroll
        for (int kk = 0; kk < 16; kk++) {
            uint32_t a0, a1, a2, a3;
            LDSM_X4(a0, a1, a2, a3, qa + kk * 32);
#pragma unroll
            for (int p = 0; p < 4; p++) {
                uint32_t b0, b1, b2, b3;
                LDSM_X4(b0, b1, b2, b3, ka + p * 16 * QROWB + kk * 32);
                mma_f16(s[2 * p][0], s[2 * p][1], s[2 * p][2], s[2 * p][3],
                        a0, a1, a2, a3, b0, b1);
                mma_f16(s[2 * p + 1][0], s[2 * p + 1][1], s[2 * p + 1][2], s[2 * p + 1][3],
                        a0, a1, a2, a3, b2, b3);
            }
        }

        // ---- online softmax (base 2); rows g and g+8 ----
        float r0 = -1e30f, r1 = -1e30f;
#pragma unroll
        for (int ni = 0; ni < 8; ni++) {
            r0 = fmaxf(r0, fmaxf(s[ni][0], s[ni][1]));
            r1 = fmaxf(r1, fmaxf(s[ni][2], s[ni][3]));
        }
        r0 = fmaxf(r0, __shfl_xor_sync(0xffffffffu, r0, 1));
        r0 = fmaxf(r0, __shfl_xor_sync(0xffffffffu, r0, 2));
        r1 = fmaxf(r1, __shfl_xor_sync(0xffffffffu, r1, 1));
        r1 = fmaxf(r1, __shfl_xor_sync(0xffffffffu, r1, 2));
        const float mn0 = fmaxf(m0, r0), mn1 = fmaxf(m1, r1);
        const float sc0 = ex2(m0 - mn0), sc1 = ex2(m1 - mn1);

        uint32_t afr[4][4];
        float ps0 = 0.f, ps1 = 0.f;
#pragma unroll
        for (int kk = 0; kk < 4; kk++) {
            const float p00 = ex2(s[2 * kk][0] - mn0);
            const float p01 = ex2(s[2 * kk][1] - mn0);
            const float p10 = ex2(s[2 * kk][2] - mn1);
            const float p11 = ex2(s[2 * kk][3] - mn1);
            const float p20 = ex2(s[2 * kk + 1][0] - mn0);
            const float p21 = ex2(s[2 * kk + 1][1] - mn0);
            const float p30 = ex2(s[2 * kk + 1][2] - mn1);
            const float p31 = ex2(s[2 * kk + 1][3] - mn1);
            ps0 += p00 + p01 + p20 + p21;
            ps1 += p10 + p11 + p30 + p31;
            afr[kk][0] = packh2(p00, p01);
            afr[kk][1] = packh2(p10, p11);
            afr[kk][2] = packh2(p20, p21);
            afr[kk][3] = packh2(p30, p31);
        }
        l0 = l0 * sc0 + ps0;
        l1 = l1 * sc1 + ps1;
        // rescale O only if some row's max moved (warp-uniform check)
        const bool nochg = (sc0 == 1.f) && (sc1 == 1.f);
        if (!__all_sync(0xffffffffu, nochg)) {
#pragma unroll
            for (int nd = 0; nd < 32; nd++) {
                acc[nd][0] *= sc0; acc[nd][1] *= sc0;
                acc[nd][2] *= sc1; acc[nd][3] *= sc1;
            }
        }
        m0 = mn0; m1 = mn1;

        // ---- O += P (16 x 64) @ Vtile (64 x 256) ----
#pragma unroll
        for (int kk = 0; kk < 4; kk++) {
#pragma unroll
            for (int p = 0; p < 16; p++) {
                uint32_t b0, b1, b2, b3;
                LDSM_X4(b0, b1, b2, b3, va + p * 16 * VROWB + kk * 32);
                mma_f16(acc[2 * p][0], acc[2 * p][1], acc[2 * p][2], acc[2 * p][3],
                        afr[kk][0], afr[kk][1], afr[kk][2], afr[kk][3], b0, b1);
                mma_f16(acc[2 * p + 1][0], acc[2 * p + 1][1],
                        acc[2 * p + 1][2], acc[2 * p + 1][3],
                        afr[kk][0], afr[kk][1], afr[kk][2], afr[kk][3], b2, b3);
            }
        }
        __syncthreads();
    }

    // ---- finalize ----
    l0 += __shfl_xor_sync(0xffffffffu, l0, 1);
    l0 += __shfl_xor_sync(0xffffffffu, l0, 2);
    l1 += __shfl_xor_sync(0xffffffffu, l1, 1);
    l1 += __shfl_xor_sync(0xffffffffu, l1, 2);
    const float inv0 = 1.f / l0, inv1 = 1.f / l1;

    __half* o0 = o + ((tokQ + w * 16 + g) * HH + h) * KDD;
    __half* o1 = o + ((tokQ + w * 16 + g + 8) * HH + h) * KDD;
#pragma unroll
    for (int nd = 0; nd < 32; nd++) {
        const int col = nd * 8 + tg * 2;
        *(__half2*)(o0 + col) = __floats2half2_rn(acc[nd][0] * inv0, acc[nd][1] * inv0);
        *(__half2*)(o1 + col) = __floats2half2_rn(acc[nd][2] * inv1, acc[nd][3] * inv1);
    }
}

// ---------------------------------------------------------------------------
// Prep kernels
// ---------------------------------------------------------------------------
__global__ void __launch_bounds__(256)
conv_h(const float* __restrict__ src, __half* __restrict__ dst, int n)
{
    int i = blockIdx.x * 256 + threadIdx.x;
    if (i < n) dst[i] = __float2half_rn(src[i]);
}

// generic weight transpose: src [K,N] fp32 -> dst [N,K] fp16
__global__ void __launch_bounds__(256)
convT_h(const float* __restrict__ src, __half* __restrict__ dst, int Kd, int Nd)
{
    __shared__ float t[32][33];
    const int tx = threadIdx.x & 31, ty = threadIdx.x >> 5;
    const int k0 = blockIdx.x * 32, n0 = blockIdx.y * 32;
#pragma unroll
    for (int i = ty; i < 32; i += 8)
        t[i][tx] = src[(long long)(k0 + i) * Nd + n0 + tx];
    __syncthreads();
#pragma unroll
    for (int i = ty; i < 32; i += 8)
        dst[(long long)(n0 + i) * Kd + k0 + tx] = __float2half_rn(t[tx][i]);
}

// pack Wq(scaled)/Wk/Wv [256,2048] -> g_wqkv [6144,256]; z selects source
__global__ void __launch_bounds__(256)
packw_qkv(const float* __restrict__ Wq, const float* __restrict__ Wk,
          const float* __restrict__ Wv, __half* __restrict__ dst)
{
    __shared__ float t[32][33];
    const int tx = threadIdx.x & 31, ty = threadIdx.x >> 5;
    const int z = blockIdx.z;
    const float* src = (z == 0) ? Wq : (z == 1) ? Wk : Wv;
    const float sc = (z == 0) ? QSCL : 1.f;
    const int k0 = blockIdx.x * 32, n0 = blockIdx.y * 32;
#pragma unroll
    for (int i = ty; i < 32; i += 8)
        t[i][tx] = src[(long long)(k0 + i) * HKD + n0 + tx];
    __syncthreads();
#pragma unroll
    for (int i = ty; i < 32; i += 8)
        dst[(long long)(z * HKD + n0 + i) * DD + k0 + tx] =
            __float2half_rn(t[tx][i] * sc);
}

__global__ void __launch_bounds__(256)
pack_bias(const float* __restrict__ bq, const float* __restrict__ bk,
          const float* __restrict__ bv, float* __restrict__ dst)
{
    const int i = blockIdx.x * 256 + threadIdx.x;   // 0..6143
    float v;
    if (i < HKD)           v = bq[i] * QSCL;
    else if (i < 2 * HKD)  v = bk[i - HKD];
    else                   v = bv[i - 2 * HKD];
    dst[i] = v;
}

// v segment of qkv [tok][6144] -> vt[bh,e,s]
__global__ void __launch_bounds__(256)
vtrans_h(const __half* __restrict__ qkv, __half* __restrict__ vt)
{
    __shared__ __half t[32][33];
    const int tx = threadIdx.x & 31, ty = threadIdx.x >> 5;
    const int bh = blockIdx.z, b = bh >> 3, h = bh & 7;
    const int s0 = blockIdx.x * 32, e0 = blockIdx.y * 32;
    const __half* vp = qkv + 2 * HKD + h * KDD;
#pragma unroll
    for (int i = ty; i < 32; i += 8)
        t[i][tx] = vp[(long long)(b * SS + s0 + i) * QKVN + e0 + tx];
    __syncthreads();
#pragma unroll
    for (int i = ty; i < 32; i += 8)
        vt[((long long)bh * KDD + e0 + i) * SS + s0 + tx] = t[tx][i];
}

// ---------------------------------------------------------------------------
// LayerNorm (+ residual)
// ---------------------------------------------------------------------------
__global__ void __launch_bounds__(256)
ln_kernel(const float* __restrict__ a, const float* __restrict__ r,
          const float* __restrict__ g, const float* __restrict__ b,
          float* __restrict__ out, __half* __restrict__ out16, int add_before)
{
    const int t = threadIdx.x;
    const long long base = (long long)blockIdx.x * DD;
    const float av = a[base + t];
    const float rv = r[base + t];
    const float val = add_before ? (av + rv) : av;

    __shared__ float sh[256];
    sh[t] = val; __syncthreads();
    for (int st = 128; st; st >>= 1) {
        if (t < st) sh[t] += sh[t + st];
        __syncthreads();
    }
    const float mean = sh[0] * (1.f / 256.f);
    __syncthreads();

    const float d = val - mean;
    sh[t] = d * d; __syncthreads();
    for (int st = 128; st; st >>= 1) {
        if (t < st) sh[t] += sh[t + st];
        __syncthreads();
    }
    const float var = sh[0] * (1.f / 256.f);

    const float y = d * rsqrtf(var + 1e-3f) * g[t] + b[t];
    const float o = add_before ? y : (y + rv);
    out[base + t] = o;
    if (out16) out16[base + t] = __float2half_rn(o);
}

// ---------------------------------------------------------------------------
// Launch
// ---------------------------------------------------------------------------
extern "C" void kernel_launch(void* const* d_in, const int* in_sizes, int n_in,
                              void* d_out, int out_size)
{
    const float* x   = (const float*)d_in[0];
    const float* Wq  = (const float*)d_in[1];
    const float* bq  = (const float*)d_in[2];
    const float* Wk  = (const float*)d_in[3];
    const float* bk  = (const float*)d_in[4];
    const float* Wv  = (const float*)d_in[5];
    const float* bv  = (const float*)d_in[6];
    const float* Wo  = (const float*)d_in[7];
    const float* bo  = (const float*)d_in[8];
    const float* g1  = (const float*)d_in[9];
    const float* be1 = (const float*)d_in[10];
    const float* W1  = (const float*)d_in[11];
    const float* bb1 = (const float*)d_in[12];
    const float* W2  = (const float*)d_in[13];
    const float* bb2 = (const float*)d_in[14];
    const float* g2  = (const float*)d_in[15];
    const float* be2 = (const float*)d_in[16];
    float* out = (float*)d_out;

    __half *qkv16, *vt16, *at16, *z16, *h16;
    __half *x16, *wqkv, *wo16, *w116, *w216;
    float *bqkv, *ao, *zz, *ff;
    cudaGetSymbolAddress((void**)&qkv16, g_qkv16);
    cudaGetSymbolAddress((void**)&vt16,  g_vt16);
    cudaGetSymbolAddress((void**)&at16,  g_at16);
    cudaGetSymbolAddress((void**)&z16,   g_z16);
    cudaGetSymbolAddress((void**)&h16,   g_h16);
    cudaGetSymbolAddress((void**)&x16,   g_x16);
    cudaGetSymbolAddress((void**)&wqkv,  g_wqkv);
    cudaGetSymbolAddress((void**)&bqkv,  g_bqkv);
    cudaGetSymbolAddress((void**)&wo16,  g_wo16);
    cudaGetSymbolAddress((void**)&w116,  g_w116);
    cudaGetSymbolAddress((void**)&w216,  g_w216);
    cudaGetSymbolAddress((void**)&ao,    g_ao);
    cudaGetSymbolAddress((void**)&zz,    g_z);
    cudaGetSymbolAddress((void**)&ff,    g_f);

    cudaFuncSetAttribute(hgemm, cudaFuncAttributeMaxDynamicSharedMemorySize, HG_SMEM);
    cudaFuncSetAttribute(fattn, cudaFuncAttributeMaxDynamicSharedMemorySize, FA_SMEM);

    const dim3 blk(256);

    // ---- prep ---------------------------------------------------------------
    conv_h<<<(MTOK * DD) / 256, blk>>>(x, x16, MTOK * DD);
    packw_qkv<<<dim3(DD / 32, HKD / 32, 3), blk>>>(Wq, Wk, Wv, wqkv);
    pack_bias<<<QKVN / 256, blk>>>(bq, bk, bv, bqkv);
    convT_h<<<dim3(HKD / 32, DD / 32), blk>>>(Wo, wo16, HKD, DD);
    convT_h<<<dim3(DD / 32, FFD / 32), blk>>>(W1, w116, DD, FFD);
    convT_h<<<dim3(FFD / 32, DD / 32), blk>>>(W2, w216, FFD, DD);

    // ---- fused QKV projection: [8192,256] @ [6144,256]^T -> [8192,6144] -----
    {
        dim3 grid(QKVN / 128, MTOK / 128, 1);
        hgemm<<<grid, blk, HG_SMEM>>>(x16, wqkv, qkv16, bqkv, DD, DD, DD, QKVN,
                                      1, 0, 0, 0, 0, 0, 0, 1.f, 0, 1);
    }

    // ---- vt[bh,e,s] from v segment ------------------------------------------
    vtrans_h<<<dim3(SS / 32, KDD / 32, BH), blk>>>(qkv16, vt16);

    // ---- fused attention ----------------------------------------------------
    fattn<<<dim3(SS / 128, BH), blk, FA_SMEM>>>(qkv16, vt16, at16);

    // ---- output projection --------------------------------------------------
    {
        dim3 grid(DD / 128, MTOK / 128, 1);
        hgemm<<<grid, blk, HG_SMEM>>>(at16, wo16, ao, bo, HKD, HKD, HKD, DD,
                                      1, 0, 0, 0, 0, 0, 0, 1.f, 0, 0);
    }

    // ---- z = LN(attn_out) + x ----------------------------------------------
    ln_kernel<<<MTOK, blk>>>(ao, x, g1, be1, zz, z16, 0);

    // ---- FFN ----------------------------------------------------------------
    {
        dim3 grid(FFD / 128, MTOK / 128, 1);
        hgemm<<<grid, blk, HG_SMEM>>>(z16, w116, h16, bb1, DD, DD, DD, FFD,
                                      1, 0, 0, 0, 0, 0, 0, 1.f, 1, 1);
    }
    {
        dim3 grid(DD / 128, MTOK / 128, 1);
        hgemm<<<grid, blk, HG_SMEM>>>(h16, w216, ff, bb2, FFD, FFD, FFD, DD,
                                      1, 0, 0, 0, 0, 0, 0, 1.f, 0, 0);
    }

    // ---- out = LN(f + z) ----------------------------------------------------
    ln_kernel<<<MTOK, blk>>>(ff, zz, g2, be2, out, nullptr, 1);
}

// round 13
// speedup vs baseline: 1.0291x; 1.0291x over previous
#include <cuda_runtime.h>
#include <cuda_fp16.h>
#include <math.h>
#include <stdint.h>

// ---------------------------------------------------------------------------
// Problem constants
// ---------------------------------------------------------------------------
#define MB   4
#define SS   2048
#define DD   256
#define HH   8
#define KDD  256
#define FFD  512
#define MTOK (MB * SS)        // 8192
#define HKD  (HH * KDD)       // 2048
#define BH   (MB * HH)        // 32
// 1/sqrt(KD) * log2(e) — folded into q so softmax runs in base 2
#define QSCL 0.0901684361f

// ---------------------------------------------------------------------------
// Static scratch (device .bss — no runtime allocation)
// ---------------------------------------------------------------------------
__device__ __align__(256) __half g_q16 [(long long)MTOK * HKD];     // [b,s,h,e]
__device__ __align__(256) __half g_k16 [(long long)MTOK * HKD];
__device__ __align__(256) __half g_v16 [(long long)MTOK * HKD];
__device__ __align__(256) __half g_vt16[(long long)BH * KDD * SS];  // [bh,e,s]
__device__ __align__(256) __half g_at16[(long long)MTOK * HKD];     // [b,s,h,e]
__device__ float g_ao[(long long)MTOK * DD];
__device__ float g_z [(long long)MTOK * DD];
__device__ __align__(256) __half g_z16 [(long long)MTOK * DD];
__device__ __align__(256) __half g_h16 [(long long)MTOK * FFD];
__device__ float g_f [(long long)MTOK * DD];
// pre-converted / pre-transposed inputs (all [N,K] fp16)
__device__ __align__(256) __half g_x16 [(long long)MTOK * DD];
__device__ __align__(256) __half g_wq16[(long long)HKD * DD];
__device__ __align__(256) __half g_wk16[(long long)HKD * DD];
__device__ __align__(256) __half g_wv16[(long long)HKD * DD];
__device__ __align__(256) __half g_wo16[(long long)DD * HKD];
__device__ __align__(256) __half g_w116[(long long)FFD * DD];
__device__ __align__(256) __half g_w216[(long long)DD * FFD];

// ---------------------------------------------------------------------------
// PTX helpers
// ---------------------------------------------------------------------------
#define CP_ASYNC16(saddr, gptr) \
    asm volatile("cp.async.cg.shared.global [%0], [%1], 16;" :: "r"(saddr), "l"(gptr))
#define CP_COMMIT()  asm volatile("cp.async.commit_group;" ::: "memory")
#define CP_WAIT_1()  asm volatile("cp.async.wait_group 1;" ::: "memory")
#define CP_WAIT_0()  asm volatile("cp.async.wait_group 0;" ::: "memory")

__device__ __forceinline__ uint32_t smem_u32(const void* p) {
    uint32_t a;
    asm("{ .reg .u64 t; cvta.to.shared.u64 t, %1; cvt.u32.u64 %0, t; }" : "=r"(a) : "l"(p));
    return a;
}

__device__ __forceinline__ void mma_f16(
    float& c0, float& c1, float& c2, float& c3,
    uint32_t a0, uint32_t a1, uint32_t a2, uint32_t a3,
    uint32_t b0, uint32_t b1)
{
    asm volatile(
        "mma.sync.aligned.m16n8k16.row.col.f32.f16.f16.f32 "
        "{%0,%1,%2,%3}, {%4,%5,%6,%7}, {%8,%9}, {%0,%1,%2,%3};"
        : "+f"(c0), "+f"(c1), "+f"(c2), "+f"(c3)
        : "r"(a0), "r"(a1), "r"(a2), "r"(a3), "r"(b0), "r"(b1));
}

#define LDSM_X4(r0, r1, r2, r3, addr) \
    asm volatile("ldmatrix.sync.aligned.m8n8.x4.shared.b16 {%0,%1,%2,%3}, [%4];" \
                 : "=r"(r0), "=r"(r1), "=r"(r2), "=r"(r3) : "r"(addr))

__device__ __forceinline__ uint32_t packh2(float lo, float hi) {
    uint32_t u;
    asm("cvt.rn.f16x2.f32 %0, %1, %2;" : "=r"(u) : "f"(hi), "f"(lo));
    return u;
}

__device__ __forceinline__ float ex2(float x) {
    float y;
    asm("ex2.approx.f32 %0, %1;" : "=f"(y) : "f"(x));
    return y;
}

// ---------------------------------------------------------------------------
// TN fp16 tensor-core GEMM (proven bit-correct; unchanged from R10/R11)
// ---------------------------------------------------------------------------
#define BKH 64
#define ROWW 36
#define OPW  (128 * ROWW)
#define STW  (2 * OPW)
#define HG_SMEM (2 * STW * 4)       // 73728 bytes

__global__ void __launch_bounds__(256)
hgemm(const __half* __restrict__ A, const __half* __restrict__ B,
      void* __restrict__ Cv, const float* __restrict__ bias,
      int K, int lda, int ldb, int ldc,
      int batch_div,
      long long sAo, long long sAi,
      long long sBo, long long sBi,
      long long sCo, long long sCi,
      float alpha, int relu, int outhalf)
{
    extern __shared__ uint32_t smw[];
    const uint32_t sbase = smem_u32(smw);

    const int z  = blockIdx.z;
    const int zo = z / batch_div;
    const int zi = z - zo * batch_div;
    A += zo * sAo + zi * sAi;
    B += zo * sBo + zi * sBi;

    const int tid  = threadIdx.x;
    const int lane = tid & 31;
    const int wrp  = tid >> 5;
    const int m0   = blockIdx.y * 128;
    const int n0   = blockIdx.x * 128;

    const int wm = (wrp & 1) * 64;
    const int wn = (wrp >> 1) * 32;
    const int g  = lane >> 2;
    const int tg = lane & 3;

    const __half* Ab = A + (long long)m0 * lda;
    const __half* Bb = B + (long long)n0 * ldb;

    float acc[4][4][4];
#pragma unroll
    for (int mi = 0; mi < 4; mi++)
#pragma unroll
        for (int ni = 0; ni < 4; ni++)
#pragma unroll
            for (int r = 0; r < 4; r++) acc[mi][ni][r] = 0.f;

    const int l15 = lane & 15;
    const int l7  = lane & 7;
    uint32_t aAddr[4], bAddr[2];
#pragma unroll
    for (int mi = 0; mi < 4; mi++)
        aAddr[mi] = sbase + ((wm + mi * 16 + l15) * ROWW + (lane >> 4) * 4) * 4;
#pragma unroll
    for (int p = 0; p < 2; p++)
        bAddr[p] = sbase + OPW * 4 +
                   ((wn + p * 16 + (lane >> 4) * 8 + l7) * ROWW +
                    ((lane >> 3) & 1) * 4) * 4;

    const int lrow = tid >> 3;
    const int lk8  = tid & 7;

    auto issue = [&](int st, int k0) {
        const uint32_t s0 = sbase + (st * STW) * 4;
#pragma unroll
        for (int i = 0; i < 4; i++) {
            const int row = lrow + i * 32;
            const uint32_t off = (row * ROWW + lk8 * 4) * 4;
            CP_ASYNC16(s0 + off,           Ab + (long long)row * lda + k0 + lk8 * 8);
            CP_ASYNC16(s0 + OPW * 4 + off, Bb + (long long)row * ldb + k0 + lk8 * 8);
        }
        CP_COMMIT();
    };

    const int T = K / BKH;
    issue(0, 0);

    for (int it = 0; it < T; it++) {
        const int st = it & 1;
        if (it + 1 < T) {
            issue(st ^ 1, (it + 1) * BKH);
            CP_WAIT_1();
        } else {
            CP_WAIT_0();
        }
        __syncthreads();

        const uint32_t sOff = (uint32_t)(st * STW) * 4;

#pragma unroll
        for (int ks = 0; ks < 4; ks++) {
            const uint32_t ko = sOff + ks * 32;
            uint32_t a[4][4];
#pragma unroll
            for (int mi = 0; mi < 4; mi++)
                LDSM_X4(a[mi][0], a[mi][1], a[mi][2], a[mi][3], aAddr[mi] + ko);
            uint32_t b[4][2];
#pragma unroll
            for (int p = 0; p < 2; p++)
                LDSM_X4(b[2 * p][0], b[2 * p][1], b[2 * p + 1][0], b[2 * p + 1][1],
                        bAddr[p] + ko);
#pragma unroll
            for (int mi = 0; mi < 4; mi++)
#pragma unroll
                for (int ni = 0; ni < 4; ni++)
                    mma_f16(acc[mi][ni][0], acc[mi][ni][1],
                            acc[mi][ni][2], acc[mi][ni][3],
                            a[mi][0], a[mi][1], a[mi][2], a[mi][3],
                            b[ni][0], b[ni][1]);
        }
        __syncthreads();
    }

    float*  Cf = (float*)Cv  + zo * sCo + zi * sCi;
    __half* Ch = (__half*)Cv + zo * sCo + zi * sCi;
#pragma unroll
    for (int mi = 0; mi < 4; mi++) {
        const int r0 = m0 + wm + mi * 16 + g;
#pragma unroll
        for (int ni = 0; ni < 4; ni++) {
            const int col = n0 + wn + ni * 8 + tg * 2;
            float v0 = acc[mi][ni][0], v1 = acc[mi][ni][1];
            float v2 = acc[mi][ni][2], v3 = acc[mi][ni][3];
            if (bias) {
                const float b0 = bias[col], b1 = bias[col + 1];
                v0 += b0; v1 += b1; v2 += b0; v3 += b1;
            }
            v0 *= alpha; v1 *= alpha; v2 *= alpha; v3 *= alpha;
            if (relu) {
                v0 = fmaxf(v0, 0.f); v1 = fmaxf(v1, 0.f);
                v2 = fmaxf(v2, 0.f); v3 = fmaxf(v3, 0.f);
            }
            if (outhalf) {
                *(__half2*)(Ch + (long long)r0 * ldc + col) =
                    __floats2half2_rn(v0, v1);
                *(__half2*)(Ch + (long long)(r0 + 8) * ldc + col) =
                    __floats2half2_rn(v2, v3);
            } else {
                *(float2*)(Cf + (long long)r0 * ldc + col)       = make_float2(v0, v1);
                *(float2*)(Cf + (long long)(r0 + 8) * ldc + col) = make_float2(v2, v3);
            }
        }
    }
}

// ---------------------------------------------------------------------------
// Fused flash attention (R11 structure + base-2 softmax + rescale skip).
// q pre-scaled by 1/sqrt(KD)*log2e. Inputs fp16: q,k [b,s,h,e]; vt [bh,e,s].
// ---------------------------------------------------------------------------
#define QROWB 528
#define VROWB 144
#define QBYT  (128 * QROWB)
#define KBYT  (64 * QROWB)
#define VBYT  (256 * VROWB)
#define STBYT (KBYT + VBYT)
#define FA_SMEM (QBYT + 2 * STBYT)   // 208896

__global__ void __launch_bounds__(256, 1)
fattn(const __half* __restrict__ q, const __half* __restrict__ k,
      const __half* __restrict__ vt, __half* __restrict__ o)
{
    extern __shared__ char fsm[];
    const uint32_t sb = smem_u32(fsm);

    const int tid = threadIdx.x, lane = tid & 31, w = tid >> 5;
    const int g = lane >> 2, tg = lane & 3;
    const int l15 = lane & 15, l7 = lane & 7;
    const int qt = blockIdx.x, bh = blockIdx.y;
    const int b = bh >> 3, h = bh & 7;
    const long long tokQ = (long long)b * SS + qt * 128;

    // ---- load Q tile (128 x 256 halves), once ----
#pragma unroll
    for (int i = 0; i < 16; i++) {
        const int c = tid + i * 256, row = c >> 5, col = c & 31;
        CP_ASYNC16(sb + row * QROWB + col * 16,
                   q + ((tokQ + row) * HH + h) * KDD + col * 8);
    }
    CP_COMMIT();

    auto loadKV = [&](int st, int kt) {
        const uint32_t kb = sb + QBYT + st * STBYT;
        const uint32_t vb = kb + KBYT;
#pragma unroll
        for (int i = 0; i < 8; i++) {
            const int c = tid + i * 256, row = c >> 5, col = c & 31;
            CP_ASYNC16(kb + row * QROWB + col * 16,
                       k + (((long long)b * SS + kt * 64 + row) * HH + h) * KDD + col * 8);
        }
#pragma unroll
        for (int i = 0; i < 8; i++) {
            const int c = tid + i * 256, d = c >> 3, kc = c & 7;
            CP_ASYNC16(vb + d * VROWB + kc * 16,
                       vt + ((long long)bh * KDD + d) * SS + kt * 64 + kc * 8);
        }
        CP_COMMIT();
    };

    loadKV(0, 0);

    float acc[32][4];
#pragma unroll
    for (int nd = 0; nd < 32; nd++)
#pragma unroll
        for (int r = 0; r < 4; r++) acc[nd][r] = 0.f;
    float m0 = -1e30f, m1 = -1e30f, l0 = 0.f, l1 = 0.f;

    const uint32_t qa = sb + (w * 16 + l15) * QROWB + (lane >> 4) * 16;

    for (int kt = 0; kt < 32; kt++) {
        const int st = kt & 1;
        if (kt + 1 < 32) { loadKV(st ^ 1, kt + 1); CP_WAIT_1(); }
        else             { CP_WAIT_0(); }
        __syncthreads();

        const uint32_t kb = sb + QBYT + st * STBYT;
        const uint32_t vb = kb + KBYT;
        const uint32_t ka = kb + ((lane >> 4) * 8 + l7) * QROWB + ((lane >> 3) & 1) * 16;
        const uint32_t va = vb + ((lane >> 4) * 8 + l7) * VROWB + ((lane >> 3) & 1) * 16;

        // ---- S = Qw (16 x 256) @ Ktile^T (64 x 256), base-2 scaled ----
        float s[8][4];
#pragma unroll
        for (int ni = 0; ni < 8; ni++)
#pragma unroll
            for (int r = 0; r < 4; r++) s[ni][r] = 0.f;

#pragma unroll
        for (int kk = 0; kk < 16; kk++) {
            uint32_t a0, a1, a2, a3;
            LDSM_X4(a0, a1, a2, a3, qa + kk * 32);
#pragma unroll
            for (int p = 0; p < 4; p++) {
                uint32_t b0, b1, b2, b3;
                LDSM_X4(b0, b1, b2, b3, ka + p * 16 * QROWB + kk * 32);
                mma_f16(s[2 * p][0], s[2 * p][1], s[2 * p][2], s[2 * p][3],
                        a0, a1, a2, a3, b0, b1);
                mma_f16(s[2 * p + 1][0], s[2 * p + 1][1], s[2 * p + 1][2], s[2 * p + 1][3],
                        a0, a1, a2, a3, b2, b3);
            }
        }

        // ---- online softmax (base 2); rows g and g+8 ----
        float r0 = -1e30f, r1 = -1e30f;
#pragma unroll
        for (int ni = 0; ni < 8; ni++) {
            r0 = fmaxf(r0, fmaxf(s[ni][0], s[ni][1]));
            r1 = fmaxf(r1, fmaxf(s[ni][2], s[ni][3]));
        }
        r0 = fmaxf(r0, __shfl_xor_sync(0xffffffffu, r0, 1));
        r0 = fmaxf(r0, __shfl_xor_sync(0xffffffffu, r0, 2));
        r1 = fmaxf(r1, __shfl_xor_sync(0xffffffffu, r1, 1));
        r1 = fmaxf(r1, __shfl_xor_sync(0xffffffffu, r1, 2));
        const float mn0 = fmaxf(m0, r0), mn1 = fmaxf(m1, r1);
        const float sc0 = ex2(m0 - mn0), sc1 = ex2(m1 - mn1);

        uint32_t afr[4][4];
        float ps0 = 0.f, ps1 = 0.f;
#pragma unroll
        for (int kk = 0; kk < 4; kk++) {
            const float p00 = ex2(s[2 * kk][0] - mn0);
            const float p01 = ex2(s[2 * kk][1] - mn0);
            const float p10 = ex2(s[2 * kk][2] - mn1);
            const float p11 = ex2(s[2 * kk][3] - mn1);
            const float p20 = ex2(s[2 * kk + 1][0] - mn0);
            const float p21 = ex2(s[2 * kk + 1][1] - mn0);
            const float p30 = ex2(s[2 * kk + 1][2] - mn1);
            const float p31 = ex2(s[2 * kk + 1][3] - mn1);
            ps0 += p00 + p01 + p20 + p21;
            ps1 += p10 + p11 + p30 + p31;
            afr[kk][0] = packh2(p00, p01);
            afr[kk][1] = packh2(p10, p11);
            afr[kk][2] = packh2(p20, p21);
            afr[kk][3] = packh2(p30, p31);
        }
        l0 = l0 * sc0 + ps0;
        l1 = l1 * sc1 + ps1;
        const bool nochg = (sc0 == 1.f) && (sc1 == 1.f);
        if (!__all_sync(0xffffffffu, nochg)) {
#pragma unroll
            for (int nd = 0; nd < 32; nd++) {
                acc[nd][0] *= sc0; acc[nd][1] *= sc0;
                acc[nd][2] *= sc1; acc[nd][3] *= sc1;
            }
        }
        m0 = mn0; m1 = mn1;

        // ---- O += P (16 x 64) @ Vtile (64 x 256) ----
#pragma unroll
        for (int kk = 0; kk < 4; kk++) {
#pragma unroll
            for (int p = 0; p < 16; p++) {
                uint32_t b0, b1, b2, b3;
                LDSM_X4(b0, b1, b2, b3, va + p * 16 * VROWB + kk * 32);
                mma_f16(acc[2 * p][0], acc[2 * p][1], acc[2 * p][2], acc[2 * p][3],
                        afr[kk][0], afr[kk][1], afr[kk][2], afr[kk][3], b0, b1);
                mma_f16(acc[2 * p + 1][0], acc[2 * p + 1][1],
                        acc[2 * p + 1][2], acc[2 * p + 1][3],
                        afr[kk][0], afr[kk][1], afr[kk][2], afr[kk][3], b2, b3);
            }
        }
        __syncthreads();
    }

    // ---- finalize ----
    l0 += __shfl_xor_sync(0xffffffffu, l0, 1);
    l0 += __shfl_xor_sync(0xffffffffu, l0, 2);
    l1 += __shfl_xor_sync(0xffffffffu, l1, 1);
    l1 += __shfl_xor_sync(0xffffffffu, l1, 2);
    const float inv0 = 1.f / l0, inv1 = 1.f / l1;

    __half* o0 = o + ((tokQ + w * 16 + g) * HH + h) * KDD;
    __half* o1 = o + ((tokQ + w * 16 + g + 8) * HH + h) * KDD;
#pragma unroll
    for (int nd = 0; nd < 32; nd++) {
        const int col = nd * 8 + tg * 2;
        *(__half2*)(o0 + col) = __floats2half2_rn(acc[nd][0] * inv0, acc[nd][1] * inv0);
        *(__half2*)(o1 + col) = __floats2half2_rn(acc[nd][2] * inv1, acc[nd][3] * inv1);
    }
}

// ---------------------------------------------------------------------------
// Prep kernels (R11 set)
// ---------------------------------------------------------------------------
__global__ void __launch_bounds__(256)
conv_h(const float* __restrict__ src, __half* __restrict__ dst, int n)
{
    int i = blockIdx.x * 256 + threadIdx.x;
    if (i < n) dst[i] = __float2half_rn(src[i]);
}

__global__ void __launch_bounds__(256)
convT_h(const float* __restrict__ src, __half* __restrict__ dst, int Kd, int Nd)
{
    __shared__ float t[32][33];
    const int tx = threadIdx.x & 31, ty = threadIdx.x >> 5;
    const int k0 = blockIdx.x * 32, n0 = blockIdx.y * 32;
#pragma unroll
    for (int i = ty; i < 32; i += 8)
        t[i][tx] = src[(long long)(k0 + i) * Nd + n0 + tx];
    __syncthreads();
#pragma unroll
    for (int i = ty; i < 32; i += 8)
        dst[(long long)(n0 + i) * Kd + k0 + tx] = __float2half_rn(t[tx][i]);
}

__global__ void __launch_bounds__(256)
vtrans_h(const __half* __restrict__ v, __half* __restrict__ vt)
{
    __shared__ __half t[32][33];
    const int tx = threadIdx.x & 31, ty = threadIdx.x >> 5;
    const int bh = blockIdx.z, b = bh >> 3, h = bh & 7;
    const int s0 = blockIdx.x * 32, e0 = blockIdx.y * 32;
#pragma unroll
    for (int i = ty; i < 32; i += 8)
        t[i][tx] = v[((long long)(b * SS + s0 + i) * HH + h) * KDD + e0 + tx];
    __syncthreads();
#pragma unroll
    for (int i = ty; i < 32; i += 8)
        vt[((long long)bh * KDD + e0 + i) * SS + s0 + tx] = t[tx][i];
}

// ---------------------------------------------------------------------------
// LayerNorm (+ residual)
// ---------------------------------------------------------------------------
__global__ void __launch_bounds__(256)
ln_kernel(const float* __restrict__ a, const float* __restrict__ r,
          const float* __restrict__ g, const float* __restrict__ b,
          float* __restrict__ out, __half* __restrict__ out16, int add_before)
{
    const int t = threadIdx.x;
    const long long base = (long long)blockIdx.x * DD;
    const float av = a[base + t];
    const float rv = r[base + t];
    const float val = add_before ? (av + rv) : av;

    __shared__ float sh[256];
    sh[t] = val; __syncthreads();
    for (int st = 128; st; st >>= 1) {
        if (t < st) sh[t] += sh[t + st];
        __syncthreads();
    }
    const float mean = sh[0] * (1.f / 256.f);
    __syncthreads();

    const float d = val - mean;
    sh[t] = d * d; __syncthreads();
    for (int st = 128; st; st >>= 1) {
        if (t < st) sh[t] += sh[t + st];
        __syncthreads();
    }
    const float var = sh[0] * (1.f / 256.f);

    const float y = d * rsqrtf(var + 1e-3f) * g[t] + b[t];
    const float o = add_before ? y : (y + rv);
    out[base + t] = o;
    if (out16) out16[base + t] = __float2half_rn(o);
}

// ---------------------------------------------------------------------------
// Launch (R11 structure; only the q-projection alpha changed)
// ---------------------------------------------------------------------------
extern "C" void kernel_launch(void* const* d_in, const int* in_sizes, int n_in,
                              void* d_out, int out_size)
{
    const float* x   = (const float*)d_in[0];
    const float* Wq  = (const float*)d_in[1];
    const float* bq  = (const float*)d_in[2];
    const float* Wk  = (const float*)d_in[3];
    const float* bk  = (const float*)d_in[4];
    const float* Wv  = (const float*)d_in[5];
    const float* bv  = (const float*)d_in[6];
    const float* Wo  = (const float*)d_in[7];
    const float* bo  = (const float*)d_in[8];
    const float* g1  = (const float*)d_in[9];
    const float* be1 = (const float*)d_in[10];
    const float* W1  = (const float*)d_in[11];
    const float* bb1 = (const float*)d_in[12];
    const float* W2  = (const float*)d_in[13];
    const float* bb2 = (const float*)d_in[14];
    const float* g2  = (const float*)d_in[15];
    const float* be2 = (const float*)d_in[16];
    float* out = (float*)d_out;

    __half *q16, *k16, *v16, *vt16, *at16, *z16, *h16;
    __half *x16, *wq16, *wk16, *wv16, *wo16, *w116, *w216;
    float *ao, *zz, *ff;
    cudaGetSymbolAddress((void**)&q16,  g_q16);
    cudaGetSymbolAddress((void**)&k16,  g_k16);
    cudaGetSymbolAddress((void**)&v16,  g_v16);
    cudaGetSymbolAddress((void**)&vt16, g_vt16);
    cudaGetSymbolAddress((void**)&at16, g_at16);
    cudaGetSymbolAddress((void**)&z16,  g_z16);
    cudaGetSymbolAddress((void**)&h16,  g_h16);
    cudaGetSymbolAddress((void**)&x16,  g_x16);
    cudaGetSymbolAddress((void**)&wq16, g_wq16);
    cudaGetSymbolAddress((void**)&wk16, g_wk16);
    cudaGetSymbolAddress((void**)&wv16, g_wv16);
    cudaGetSymbolAddress((void**)&wo16, g_wo16);
    cudaGetSymbolAddress((void**)&w116, g_w116);
    cudaGetSymbolAddress((void**)&w216, g_w216);
    cudaGetSymbolAddress((void**)&ao,   g_ao);
    cudaGetSymbolAddress((void**)&zz,   g_z);
    cudaGetSymbolAddress((void**)&ff,   g_f);

    cudaFuncSetAttribute(hgemm, cudaFuncAttributeMaxDynamicSharedMemorySize, HG_SMEM);
    cudaFuncSetAttribute(fattn, cudaFuncAttributeMaxDynamicSharedMemorySize, FA_SMEM);

    const dim3 blk(256);

    // ---- prep: x -> fp16; weights -> [N,K] fp16 -----------------------------
    conv_h<<<(MTOK * DD) / 256, blk>>>(x, x16, MTOK * DD);
    convT_h<<<dim3(DD / 32, HKD / 32), blk>>>(Wq, wq16, DD, HKD);
    convT_h<<<dim3(DD / 32, HKD / 32), blk>>>(Wk, wk16, DD, HKD);
    convT_h<<<dim3(DD / 32, HKD / 32), blk>>>(Wv, wv16, DD, HKD);
    convT_h<<<dim3(HKD / 32, DD / 32), blk>>>(Wo, wo16, HKD, DD);
    convT_h<<<dim3(DD / 32, FFD / 32), blk>>>(W1, w116, DD, FFD);
    convT_h<<<dim3(FFD / 32, DD / 32), blk>>>(W2, w216, FFD, DD);

    // ---- Q/K/V projections (TN) -> [b,s,h,e] fp16 (q scaled for base-2) -----
    {
        dim3 grid(HKD / 128, MTOK / 128, 1);
        hgemm<<<grid, blk, HG_SMEM>>>(x16, wq16, q16, bq, DD, DD, DD, HKD,
                                      1, 0, 0, 0, 0, 0, 0, QSCL, 0, 1);
        hgemm<<<grid, blk, HG_SMEM>>>(x16, wk16, k16, bk, DD, DD, DD, HKD,
                                      1, 0, 0, 0, 0, 0, 0, 1.f, 0, 1);
        hgemm<<<grid, blk, HG_SMEM>>>(x16, wv16, v16, bv, DD, DD, DD, HKD,
                                      1, 0, 0, 0, 0, 0, 0, 1.f, 0, 1);
    }

    // ---- vt[bh,e,s] ---------------------------------------------------------
    vtrans_h<<<dim3(SS / 32, KDD / 32, BH), blk>>>(v16, vt16);

    // ---- fused attention ----------------------------------------------------
    fattn<<<dim3(SS / 128, BH), blk, FA_SMEM>>>(q16, k16, vt16, at16);

    // ---- output projection --------------------------------------------------
    {
        dim3 grid(DD / 128, MTOK / 128, 1);
        hgemm<<<grid, blk, HG_SMEM>>>(at16, wo16, ao, bo, HKD, HKD, HKD, DD,
                                      1, 0, 0, 0, 0, 0, 0, 1.f, 0, 0);
    }

    // ---- z = LN(attn_out) + x ----------------------------------------------
    ln_kernel<<<MTOK, blk>>>(ao, x, g1, be1, zz, z16, 0);

    // ---- FFN ----------------------------------------------------------------
    {
        dim3 grid(FFD / 128, MTOK / 128, 1);
        hgemm<<<grid, blk, HG_SMEM>>>(z16, w116, h16, bb1, DD, DD, DD, FFD,
                                      1, 0, 0, 0, 0, 0, 0, 1.f, 1, 1);
    }
    {
        dim3 grid(DD / 128, MTOK / 128, 1);
        hgemm<<<grid, blk, HG_SMEM>>>(h16, w216, ff, bb2, FFD, FFD, FFD, DD,
                                      1, 0, 0, 0, 0, 0, 0, 1.f, 0, 0);
    }

    // ---- out = LN(f + z) ----------------------------------------------------
    ln_kernel<<<MTOK, blk>>>(ff, zz, g2, be2, out, nullptr, 1);
}

// round 15
// speedup vs baseline: 1.0889x; 1.0581x over previous
#include <cuda_runtime.h>
#include <cuda_fp16.h>
#include <math.h>
#include <stdint.h>

// ---------------------------------------------------------------------------
// Problem constants
// ---------------------------------------------------------------------------
#define MB   4
#define SS   2048
#define DD   256
#define HH   8
#define KDD  256
#define FFD  512
#define MTOK (MB * SS)        // 8192
#define HKD  (HH * KDD)       // 2048
#define BH   (MB * HH)        // 32

// ---------------------------------------------------------------------------
// Static scratch (device .bss — no runtime allocation)
// ---------------------------------------------------------------------------
__device__ __align__(256) __half g_q16 [(long long)MTOK * HKD];     // [b,s,h,e]
__device__ __align__(256) __half g_k16 [(long long)MTOK * HKD];
__device__ __align__(256) __half g_v16 [(long long)MTOK * HKD];
__device__ __align__(256) __half g_vt16[(long long)BH * KDD * SS];  // [bh,e,s]
__device__ __align__(256) __half g_at16[(long long)MTOK * HKD];     // [b,s,h,e]
__device__ float g_ao[(long long)MTOK * DD];
__device__ float g_z [(long long)MTOK * DD];
__device__ __align__(256) __half g_z16 [(long long)MTOK * DD];
__device__ __align__(256) __half g_h16 [(long long)MTOK * FFD];
__device__ float g_f [(long long)MTOK * DD];
// pre-converted / pre-transposed inputs (all [N,K] fp16)
__device__ __align__(256) __half g_x16 [(long long)MTOK * DD];
__device__ __align__(256) __half g_wq16[(long long)HKD * DD];
__device__ __align__(256) __half g_wk16[(long long)HKD * DD];
__device__ __align__(256) __half g_wv16[(long long)HKD * DD];
__device__ __align__(256) __half g_wo16[(long long)DD * HKD];
__device__ __align__(256) __half g_w116[(long long)FFD * DD];
__device__ __align__(256) __half g_w216[(long long)DD * FFD];

// ---------------------------------------------------------------------------
// PTX helpers
// ---------------------------------------------------------------------------
#define CP_ASYNC16(saddr, gptr) \
    asm volatile("cp.async.cg.shared.global [%0], [%1], 16;" :: "r"(saddr), "l"(gptr))
#define CP_COMMIT()  asm volatile("cp.async.commit_group;" ::: "memory")
#define CP_WAIT_1()  asm volatile("cp.async.wait_group 1;" ::: "memory")
#define CP_WAIT_0()  asm volatile("cp.async.wait_group 0;" ::: "memory")

__device__ __forceinline__ uint32_t smem_u32(const void* p) {
    uint32_t a;
    asm("{ .reg .u64 t; cvta.to.shared.u64 t, %1; cvt.u32.u64 %0, t; }" : "=r"(a) : "l"(p));
    return a;
}

__device__ __forceinline__ void mma_f16(
    float& c0, float& c1, float& c2, float& c3,
    uint32_t a0, uint32_t a1, uint32_t a2, uint32_t a3,
    uint32_t b0, uint32_t b1)
{
    asm volatile(
        "mma.sync.aligned.m16n8k16.row.col.f32.f16.f16.f32 "
        "{%0,%1,%2,%3}, {%4,%5,%6,%7}, {%8,%9}, {%0,%1,%2,%3};"
        : "+f"(c0), "+f"(c1), "+f"(c2), "+f"(c3)
        : "r"(a0), "r"(a1), "r"(a2), "r"(a3), "r"(b0), "r"(b1));
}

#define LDSM_X4(r0, r1, r2, r3, addr) \
    asm volatile("ldmatrix.sync.aligned.m8n8.x4.shared.b16 {%0,%1,%2,%3}, [%4];" \
                 : "=r"(r0), "=r"(r1), "=r"(r2), "=r"(r3) : "r"(addr))

__device__ __forceinline__ uint32_t packh2(float lo, float hi) {
    uint32_t u;
    asm("cvt.rn.f16x2.f32 %0, %1, %2;" : "=r"(u) : "f"(hi), "f"(lo));
    return u;
}

// ---------------------------------------------------------------------------
// TN fp16 tensor-core GEMM (proven bit-correct; unchanged)
// ---------------------------------------------------------------------------
#define BKH 64
#define ROWW 36
#define OPW  (128 * ROWW)
#define STW  (2 * OPW)
#define HG_SMEM (2 * STW * 4)       // 73728 bytes

__global__ void __launch_bounds__(256)
hgemm(const __half* __restrict__ A, const __half* __restrict__ B,
      void* __restrict__ Cv, const float* __restrict__ bias,
      int K, int lda, int ldb, int ldc,
      int batch_div,
      long long sAo, long long sAi,
      long long sBo, long long sBi,
      long long sCo, long long sCi,
      float alpha, int relu, int outhalf)
{
    extern __shared__ uint32_t smw[];
    const uint32_t sbase = smem_u32(smw);

    const int z  = blockIdx.z;
    const int zo = z / batch_div;
    const int zi = z - zo * batch_div;
    A += zo * sAo + zi * sAi;
    B += zo * sBo + zi * sBi;

    const int tid  = threadIdx.x;
    const int lane = tid & 31;
    const int wrp  = tid >> 5;
    const int m0   = blockIdx.y * 128;
    const int n0   = blockIdx.x * 128;

    const int wm = (wrp & 1) * 64;
    const int wn = (wrp >> 1) * 32;
    const int g  = lane >> 2;
    const int tg = lane & 3;

    const __half* Ab = A + (long long)m0 * lda;
    const __half* Bb = B + (long long)n0 * ldb;

    float acc[4][4][4];
#pragma unroll
    for (int mi = 0; mi < 4; mi++)
#pragma unroll
        for (int ni = 0; ni < 4; ni++)
#pragma unroll
            for (int r = 0; r < 4; r++) acc[mi][ni][r] = 0.f;

    const int l15 = lane & 15;
    const int l7  = lane & 7;
    uint32_t aAddr[4], bAddr[2];
#pragma unroll
    for (int mi = 0; mi < 4; mi++)
        aAddr[mi] = sbase + ((wm + mi * 16 + l15) * ROWW + (lane >> 4) * 4) * 4;
#pragma unroll
    for (int p = 0; p < 2; p++)
        bAddr[p] = sbase + OPW * 4 +
                   ((wn + p * 16 + (lane >> 4) * 8 + l7) * ROWW +
                    ((lane >> 3) & 1) * 4) * 4;

    const int lrow = tid >> 3;
    const int lk8  = tid & 7;

    auto issue = [&](int st, int k0) {
        const uint32_t s0 = sbase + (st * STW) * 4;
#pragma unroll
        for (int i = 0; i < 4; i++) {
            const int row = lrow + i * 32;
            const uint32_t off = (row * ROWW + lk8 * 4) * 4;
            CP_ASYNC16(s0 + off,           Ab + (long long)row * lda + k0 + lk8 * 8);
            CP_ASYNC16(s0 + OPW * 4 + off, Bb + (long long)row * ldb + k0 + lk8 * 8);
        }
        CP_COMMIT();
    };

    const int T = K / BKH;
    issue(0, 0);

    for (int it = 0; it < T; it++) {
        const int st = it & 1;
        if (it + 1 < T) {
            issue(st ^ 1, (it + 1) * BKH);
            CP_WAIT_1();
        } else {
            CP_WAIT_0();
        }
        __syncthreads();

        const uint32_t sOff = (uint32_t)(st * STW) * 4;

#pragma unroll
        for (int ks = 0; ks < 4; ks++) {
            const uint32_t ko = sOff + ks * 32;
            uint32_t a[4][4];
#pragma unroll
            for (int mi = 0; mi < 4; mi++)
                LDSM_X4(a[mi][0], a[mi][1], a[mi][2], a[mi][3], aAddr[mi] + ko);
            uint32_t b[4][2];
#pragma unroll
            for (int p = 0; p < 2; p++)
                LDSM_X4(b[2 * p][0], b[2 * p][1], b[2 * p + 1][0], b[2 * p + 1][1],
                        bAddr[p] + ko);
#pragma unroll
            for (int mi = 0; mi < 4; mi++)
#pragma unroll
                for (int ni = 0; ni < 4; ni++)
                    mma_f16(acc[mi][ni][0], acc[mi][ni][1],
                            acc[mi][ni][2], acc[mi][ni][3],
                            a[mi][0], a[mi][1], a[mi][2], a[mi][3],
                            b[ni][0], b[ni][1]);
        }
        __syncthreads();
    }

    float*  Cf = (float*)Cv  + zo * sCo + zi * sCi;
    __half* Ch = (__half*)Cv + zo * sCo + zi * sCi;
#pragma unroll
    for (int mi = 0; mi < 4; mi++) {
        const int r0 = m0 + wm + mi * 16 + g;
#pragma unroll
        for (int ni = 0; ni < 4; ni++) {
            const int col = n0 + wn + ni * 8 + tg * 2;
            float v0 = acc[mi][ni][0], v1 = acc[mi][ni][1];
            float v2 = acc[mi][ni][2], v3 = acc[mi][ni][3];
            if (bias) {
                const float b0 = bias[col], b1 = bias[col + 1];
                v0 += b0; v1 += b1; v2 += b0; v3 += b1;
            }
            v0 *= alpha; v1 *= alpha; v2 *= alpha; v3 *= alpha;
            if (relu) {
                v0 = fmaxf(v0, 0.f); v1 = fmaxf(v1, 0.f);
                v2 = fmaxf(v2, 0.f); v3 = fmaxf(v3, 0.f);
            }
            if (outhalf) {
                *(__half2*)(Ch + (long long)r0 * ldc + col) =
                    __floats2half2_rn(v0, v1);
                *(__half2*)(Ch + (long long)(r0 + 8) * ldc + col) =
                    __floats2half2_rn(v2, v3);
            } else {
                *(float2*)(Cf + (long long)r0 * ldc + col)       = make_float2(v0, v1);
                *(float2*)(Cf + (long long)(r0 + 8) * ldc + col) = make_float2(v2, v3);
            }
        }
    }
}

// ---------------------------------------------------------------------------
// Fused flash attention — R11 VERBATIM (natural-base softmax, unconditional
// rescale). q pre-scaled by 1/sqrt(KD). q,k [b,s,h,e]; vt [bh,e,s].
// ---------------------------------------------------------------------------
#define QROWB 528
#define VROWB 144
#define QBYT  (128 * QROWB)
#define KBYT  (64 * QROWB)
#define VBYT  (256 * VROWB)
#define STBYT (KBYT + VBYT)
#define FA_SMEM (QBYT + 2 * STBYT)   // 208896

__global__ void __launch_bounds__(256, 1)
fattn(const __half* __restrict__ q, const __half* __restrict__ k,
      const __half* __restrict__ vt, __half* __restrict__ o)
{
    extern __shared__ char fsm[];
    const uint32_t sb = smem_u32(fsm);

    const int tid = threadIdx.x, lane = tid & 31, w = tid >> 5;
    const int g = lane >> 2, tg = lane & 3;
    const int l15 = lane & 15, l7 = lane & 7;
    const int qt = blockIdx.x, bh = blockIdx.y;
    const int b = bh >> 3, h = bh & 7;
    const long long tokQ = (long long)b * SS + qt * 128;

    // ---- load Q tile (128 x 256 halves), once ----
#pragma unroll
    for (int i = 0; i < 16; i++) {
        const int c = tid + i * 256, row = c >> 5, col = c & 31;
        CP_ASYNC16(sb + row * QROWB + col * 16,
                   q + ((tokQ + row) * HH + h) * KDD + col * 8);
    }
    CP_COMMIT();

    auto loadKV = [&](int st, int kt) {
        const uint32_t kb = sb + QBYT + st * STBYT;
        const uint32_t vb = kb + KBYT;
#pragma unroll
        for (int i = 0; i < 8; i++) {
            const int c = tid + i * 256, row = c >> 5, col = c & 31;
            CP_ASYNC16(kb + row * QROWB + col * 16,
                       k + (((long long)b * SS + kt * 64 + row) * HH + h) * KDD + col * 8);
        }
#pragma unroll
        for (int i = 0; i < 8; i++) {
            const int c = tid + i * 256, d = c >> 3, kc = c & 7;
            CP_ASYNC16(vb + d * VROWB + kc * 16,
                       vt + ((long long)bh * KDD + d) * SS + kt * 64 + kc * 8);
        }
        CP_COMMIT();
    };

    loadKV(0, 0);

    float acc[32][4];
#pragma unroll
    for (int nd = 0; nd < 32; nd++)
#pragma unroll
        for (int r = 0; r < 4; r++) acc[nd][r] = 0.f;
    float m0 = -1e30f, m1 = -1e30f, l0 = 0.f, l1 = 0.f;

    const uint32_t qa = sb + (w * 16 + l15) * QROWB + (lane >> 4) * 16;

    for (int kt = 0; kt < 32; kt++) {
        const int st = kt & 1;
        if (kt + 1 < 32) { loadKV(st ^ 1, kt + 1); CP_WAIT_1(); }
        else             { CP_WAIT_0(); }
        __syncthreads();

        const uint32_t kb = sb + QBYT + st * STBYT;
        const uint32_t vb = kb + KBYT;
        const uint32_t ka = kb + ((lane >> 4) * 8 + l7) * QROWB + ((lane >> 3) & 1) * 16;
        const uint32_t va = vb + ((lane >> 4) * 8 + l7) * VROWB + ((lane >> 3) & 1) * 16;

        // ---- S = Qw (16 x 256) @ Ktile^T (64 x 256) ----
        float s[8][4];
#pragma unroll
        for (int ni = 0; ni < 8; ni++)
#pragma unroll
            for (int r = 0; r < 4; r++) s[ni][r] = 0.f;

#pragma unroll
        for (int kk = 0; kk < 16; kk++) {
            uint32_t a0, a1, a2, a3;
            LDSM_X4(a0, a1, a2, a3, qa + kk * 32);
#pragma unroll
            for (int p = 0; p < 4; p++) {
                uint32_t b0, b1, b2, b3;
                LDSM_X4(b0, b1, b2, b3, ka + p * 16 * QROWB + kk * 32);
                mma_f16(s[2 * p][0], s[2 * p][1], s[2 * p][2], s[2 * p][3],
                        a0, a1, a2, a3, b0, b1);
                mma_f16(s[2 * p + 1][0], s[2 * p + 1][1], s[2 * p + 1][2], s[2 * p + 1][3],
                        a0, a1, a2, a3, b2, b3);
            }
        }

        // ---- online softmax update (rows g and g+8) ----
        float r0 = -1e30f, r1 = -1e30f;
#pragma unroll
        for (int ni = 0; ni < 8; ni++) {
            r0 = fmaxf(r0, fmaxf(s[ni][0], s[ni][1]));
            r1 = fmaxf(r1, fmaxf(s[ni][2], s[ni][3]));
        }
        r0 = fmaxf(r0, __shfl_xor_sync(0xffffffffu, r0, 1));
        r0 = fmaxf(r0, __shfl_xor_sync(0xffffffffu, r0, 2));
        r1 = fmaxf(r1, __shfl_xor_sync(0xffffffffu, r1, 1));
        r1 = fmaxf(r1, __shfl_xor_sync(0xffffffffu, r1, 2));
        const float mn0 = fmaxf(m0, r0), mn1 = fmaxf(m1, r1);
        const float sc0 = __expf(m0 - mn0), sc1 = __expf(m1 - mn1);

        uint32_t afr[4][4];
        float ps0 = 0.f, ps1 = 0.f;
#pragma unroll
        for (int kk = 0; kk < 4; kk++) {
            const float p00 = __expf(s[2 * kk][0] - mn0);
            const float p01 = __expf(s[2 * kk][1] - mn0);
            const float p10 = __expf(s[2 * kk][2] - mn1);
            const float p11 = __expf(s[2 * kk][3] - mn1);
            const float p20 = __expf(s[2 * kk + 1][0] - mn0);
            const float p21 = __expf(s[2 * kk + 1][1] - mn0);
            const float p30 = __expf(s[2 * kk + 1][2] - mn1);
            const float p31 = __expf(s[2 * kk + 1][3] - mn1);
            ps0 += p00 + p01 + p20 + p21;
            ps1 += p10 + p11 + p30 + p31;
            afr[kk][0] = packh2(p00, p01);
            afr[kk][1] = packh2(p10, p11);
            afr[kk][2] = packh2(p20, p21);
            afr[kk][3] = packh2(p30, p31);
        }
        l0 = l0 * sc0 + ps0;
        l1 = l1 * sc1 + ps1;
#pragma unroll
        for (int nd = 0; nd < 32; nd++) {
            acc[nd][0] *= sc0; acc[nd][1] *= sc0;
            acc[nd][2] *= sc1; acc[nd][3] *= sc1;
        }
        m0 = mn0; m1 = mn1;

        // ---- O += P (16 x 64) @ Vtile (64 x 256) ----
#pragma unroll
        for (int kk = 0; kk < 4; kk++) {
#pragma unroll
            for (int p = 0; p < 16; p++) {
                uint32_t b0, b1, b2, b3;
                LDSM_X4(b0, b1, b2, b3, va + p * 16 * VROWB + kk * 32);
                mma_f16(acc[2 * p][0], acc[2 * p][1], acc[2 * p][2], acc[2 * p][3],
                        afr[kk][0], afr[kk][1], afr[kk][2], afr[kk][3], b0, b1);
                mma_f16(acc[2 * p + 1][0], acc[2 * p + 1][1],
                        acc[2 * p + 1][2], acc[2 * p + 1][3],
                        afr[kk][0], afr[kk][1], afr[kk][2], afr[kk][3], b2, b3);
            }
        }
        __syncthreads();
    }

    // ---- finalize: divide by l, store fp16 [b,s,h,e] ----
    l0 += __shfl_xor_sync(0xffffffffu, l0, 1);
    l0 += __shfl_xor_sync(0xffffffffu, l0, 2);
    l1 += __shfl_xor_sync(0xffffffffu, l1, 1);
    l1 += __shfl_xor_sync(0xffffffffu, l1, 2);
    const float inv0 = 1.f / l0, inv1 = 1.f / l1;

    __half* o0 = o + ((tokQ + w * 16 + g) * HH + h) * KDD;
    __half* o1 = o + ((tokQ + w * 16 + g + 8) * HH + h) * KDD;
#pragma unroll
    for (int nd = 0; nd < 32; nd++) {
        const int col = nd * 8 + tg * 2;
        *(__half2*)(o0 + col) = __floats2half2_rn(acc[nd][0] * inv0, acc[nd][1] * inv0);
        *(__half2*)(o1 + col) = __floats2half2_rn(acc[nd][2] * inv1, acc[nd][3] * inv1);
    }
}

// ---------------------------------------------------------------------------
// Prep: x -> fp16 (unchanged)
// ---------------------------------------------------------------------------
__global__ void __launch_bounds__(256)
conv_h(const float* __restrict__ src, __half* __restrict__ dst, int n)
{
    int i = blockIdx.x * 256 + threadIdx.x;
    if (i < n) dst[i] = __float2half_rn(src[i]);
}

// Batched weight transpose: all six [K,N] fp32 -> [N,K] fp16 in ONE launch.
// Block-range -> segment lookup; same 32x33 transpose body as convT_h.
__global__ void __launch_bounds__(256)
convT_all(const float* __restrict__ Wq, const float* __restrict__ Wk,
          const float* __restrict__ Wv, const float* __restrict__ Wo,
          const float* __restrict__ W1, const float* __restrict__ W2,
          __half* __restrict__ wq, __half* __restrict__ wk,
          __half* __restrict__ wv, __half* __restrict__ wo,
          __half* __restrict__ w1, __half* __restrict__ w2)
{
    const int bid = blockIdx.x;
    const float* src; __half* dst; int Kd, Nd, t;
    if (bid < 512)       { src = Wq; dst = wq; Kd = DD;  Nd = HKD; t = bid; }
    else if (bid < 1024) { src = Wk; dst = wk; Kd = DD;  Nd = HKD; t = bid - 512; }
    else if (bid < 1536) { src = Wv; dst = wv; Kd = DD;  Nd = HKD; t = bid - 1024; }
    else if (bid < 2048) { src = Wo; dst = wo; Kd = HKD; Nd = DD;  t = bid - 1536; }
    else if (bid < 2176) { src = W1; dst = w1; Kd = DD;  Nd = FFD; t = bid - 2048; }
    else                 { src = W2; dst = w2; Kd = FFD; Nd = DD;  t = bid - 2176; }
    const int nK = Kd / 32;
    const int k0 = (t % nK) * 32, n0 = (t / nK) * 32;

    __shared__ float tt[32][33];
    const int tx = threadIdx.x & 31, ty = threadIdx.x >> 5;
#pragma unroll
    for (int i = ty; i < 32; i += 8)
        tt[i][tx] = src[(long long)(k0 + i) * Nd + n0 + tx];
    __syncthreads();
#pragma unroll
    for (int i = ty; i < 32; i += 8)
        dst[(long long)(n0 + i) * Kd + k0 + tx] = __float2half_rn(tt[tx][i]);
}

// v[b,s,h,e] fp16 -> vt[bh,e,s] fp16 (unchanged)
__global__ void __launch_bounds__(256)
vtrans_h(const __half* __restrict__ v, __half* __restrict__ vt)
{
    __shared__ __half t[32][33];
    const int tx = threadIdx.x & 31, ty = threadIdx.x >> 5;
    const int bh = blockIdx.z, b = bh >> 3, h = bh & 7;
    const int s0 = blockIdx.x * 32, e0 = blockIdx.y * 32;
#pragma unroll
    for (int i = ty; i < 32; i += 8)
        t[i][tx] = v[((long long)(b * SS + s0 + i) * HH + h) * KDD + e0 + tx];
    __syncthreads();
#pragma unroll
    for (int i = ty; i < 32; i += 8)
        vt[((long long)bh * KDD + e0 + i) * SS + s0 + tx] = t[tx][i];
}

// ---------------------------------------------------------------------------
// LayerNorm (+ residual) — unchanged
// ---------------------------------------------------------------------------
__global__ void __launch_bounds__(256)
ln_kernel(const float* __restrict__ a, const float* __restrict__ r,
          const float* __restrict__ g, const float* __restrict__ b,
          float* __restrict__ out, __half* __restrict__ out16, int add_before)
{
    const int t = threadIdx.x;
    const long long base = (long long)blockIdx.x * DD;
    const float av = a[base + t];
    const float rv = r[base + t];
    const float val = add_before ? (av + rv) : av;

    __shared__ float sh[256];
    sh[t] = val; __syncthreads();
    for (int st = 128; st; st >>= 1) {
        if (t < st) sh[t] += sh[t + st];
        __syncthreads();
    }
    const float mean = sh[0] * (1.f / 256.f);
    __syncthreads();

    const float d = val - mean;
    sh[t] = d * d; __syncthreads();
    for (int st = 128; st; st >>= 1) {
        if (t < st) sh[t] += sh[t + st];
        __syncthreads();
    }
    const float var = sh[0] * (1.f / 256.f);

    const float y = d * rsqrtf(var + 1e-3f) * g[t] + b[t];
    const float o = add_before ? y : (y + rv);
    out[base + t] = o;
    if (out16) out16[base + t] = __float2half_rn(o);
}

// ---------------------------------------------------------------------------
// Launch (R11 structure; prep transposes merged into one launch)
// ---------------------------------------------------------------------------
extern "C" void kernel_launch(void* const* d_in, const int* in_sizes, int n_in,
                              void* d_out, int out_size)
{
    const float* x   = (const float*)d_in[0];
    const float* Wq  = (const float*)d_in[1];
    const float* bq  = (const float*)d_in[2];
    const float* Wk  = (const float*)d_in[3];
    const float* bk  = (const float*)d_in[4];
    const float* Wv  = (const float*)d_in[5];
    const float* bv  = (const float*)d_in[6];
    const float* Wo  = (const float*)d_in[7];
    const float* bo  = (const float*)d_in[8];
    const float* g1  = (const float*)d_in[9];
    const float* be1 = (const float*)d_in[10];
    const float* W1  = (const float*)d_in[11];
    const float* bb1 = (const float*)d_in[12];
    const float* W2  = (const float*)d_in[13];
    const float* bb2 = (const float*)d_in[14];
    const float* g2  = (const float*)d_in[15];
    const float* be2 = (const float*)d_in[16];
    float* out = (float*)d_out;

    __half *q16, *k16, *v16, *vt16, *at16, *z16, *h16;
    __half *x16, *wq16, *wk16, *wv16, *wo16, *w116, *w216;
    float *ao, *zz, *ff;
    cudaGetSymbolAddress((void**)&q16,  g_q16);
    cudaGetSymbolAddress((void**)&k16,  g_k16);
    cudaGetSymbolAddress((void**)&v16,  g_v16);
    cudaGetSymbolAddress((void**)&vt16, g_vt16);
    cudaGetSymbolAddress((void**)&at16, g_at16);
    cudaGetSymbolAddress((void**)&z16,  g_z16);
    cudaGetSymbolAddress((void**)&h16,  g_h16);
    cudaGetSymbolAddress((void**)&x16,  g_x16);
    cudaGetSymbolAddress((void**)&wq16, g_wq16);
    cudaGetSymbolAddress((void**)&wk16, g_wk16);
    cudaGetSymbolAddress((void**)&wv16, g_wv16);
    cudaGetSymbolAddress((void**)&wo16, g_wo16);
    cudaGetSymbolAddress((void**)&w116, g_w116);
    cudaGetSymbolAddress((void**)&w216, g_w216);
    cudaGetSymbolAddress((void**)&ao,   g_ao);
    cudaGetSymbolAddress((void**)&zz,   g_z);
    cudaGetSymbolAddress((void**)&ff,   g_f);

    cudaFuncSetAttribute(hgemm, cudaFuncAttributeMaxDynamicSharedMemorySize, HG_SMEM);
    cudaFuncSetAttribute(fattn, cudaFuncAttributeMaxDynamicSharedMemorySize, FA_SMEM);

    const dim3 blk(256);
    const float qscale = 1.0f / 16.0f;   // 1/sqrt(KD)

    // ---- prep: 2 launches ---------------------------------------------------
    conv_h<<<(MTOK * DD) / 256, blk>>>(x, x16, MTOK * DD);
    convT_all<<<2304, blk>>>(Wq, Wk, Wv, Wo, W1, W2,
                             wq16, wk16, wv16, wo16, w116, w216);

    // ---- Q/K/V projections (TN) -> [b,s,h,e] fp16 (q scaled) ----------------
    {
        dim3 grid(HKD / 128, MTOK / 128, 1);
        hgemm<<<grid, blk, HG_SMEM>>>(x16, wq16, q16, bq, DD, DD, DD, HKD,
                                      1, 0, 0, 0, 0, 0, 0, qscale, 0, 1);
        hgemm<<<grid, blk, HG_SMEM>>>(x16, wk16, k16, bk, DD, DD, DD, HKD,
                                      1, 0, 0, 0, 0, 0, 0, 1.f, 0, 1);
        hgemm<<<grid, blk, HG_SMEM>>>(x16, wv16, v16, bv, DD, DD, DD, HKD,
                                      1, 0, 0, 0, 0, 0, 0, 1.f, 0, 1);
    }

    // ---- vt[bh,e,s] ---------------------------------------------------------
    vtrans_h<<<dim3(SS / 32, KDD / 32, BH), blk>>>(v16, vt16);

    // ---- fused attention ----------------------------------------------------
    fattn<<<dim3(SS / 128, BH), blk, FA_SMEM>>>(q16, k16, vt16, at16);

    // ---- output projection --------------------------------------------------
    {
        dim3 grid(DD / 128, MTOK / 128, 1);
        hgemm<<<grid, blk, HG_SMEM>>>(at16, wo16, ao, bo, HKD, HKD, HKD, DD,
                                      1, 0, 0, 0, 0, 0, 0, 1.f, 0, 0);
    }

    // ---- z = LN(attn_out) + x ----------------------------------------------
    ln_kernel<<<MTOK, blk>>>(ao, x, g1, be1, zz, z16, 0);

    // ---- FFN ----------------------------------------------------------------
    {
        dim3 grid(FFD / 128, MTOK / 128, 1);
        hgemm<<<grid, blk, HG_SMEM>>>(z16, w116, h16, bb1, DD, DD, DD, FFD,
                                      1, 0, 0, 0, 0, 0, 0, 1.f, 1, 1);
    }
    {
        dim3 grid(DD / 128, MTOK / 128, 1);
        hgemm<<<grid, blk, HG_SMEM>>>(h16, w216, ff, bb2, FFD, FFD, FFD, DD,
                                      1, 0, 0, 0, 0, 0, 0, 1.f, 0, 0);
    }

    // ---- out = LN(f + z) ----------------------------------------------------
    ln_kernel<<<MTOK, blk>>>(ff, zz, g2, be2, out, nullptr, 1);
}

// round 16
// speedup vs baseline: 1.0935x; 1.0042x over previous
#include <cuda_runtime.h>
#include <cuda_fp16.h>
#include <math.h>
#include <stdint.h>

// ---------------------------------------------------------------------------
// Problem constants
// ---------------------------------------------------------------------------
#define MB   4
#define SS   2048
#define DD   256
#define HH   8
#define KDD  256
#define FFD  512
#define MTOK (MB * SS)        // 8192
#define HKD  (HH * KDD)       // 2048
#define BH   (MB * HH)        // 32

// ---------------------------------------------------------------------------
// Static scratch (device .bss — no runtime allocation)
// ---------------------------------------------------------------------------
__device__ __align__(256) __half g_qkv3[(long long)3 * MTOK * HKD]; // q|k|v slabs
__device__ __align__(256) __half g_vt16[(long long)BH * KDD * SS];  // [bh,e,s]
__device__ __align__(256) __half g_at16[(long long)MTOK * HKD];     // [b,s,h,e]
__device__ float g_ao[(long long)MTOK * DD];
__device__ float g_z [(long long)MTOK * DD];
__device__ __align__(256) __half g_z16 [(long long)MTOK * DD];
__device__ __align__(256) __half g_h16 [(long long)MTOK * FFD];
__device__ float g_f [(long long)MTOK * DD];
// pre-converted / pre-transposed inputs
__device__ __align__(256) __half g_x16  [(long long)MTOK * DD];
__device__ __align__(256) __half g_wqkv3[(long long)3 * HKD * DD];  // [z][N][K]
__device__ float                 g_b3   [3 * HKD];
__device__ __align__(256) __half g_wo16[(long long)DD * HKD];
__device__ __align__(256) __half g_w116[(long long)FFD * DD];
__device__ __align__(256) __half g_w216[(long long)DD * FFD];

// ---------------------------------------------------------------------------
// PTX helpers
// ---------------------------------------------------------------------------
#define CP_ASYNC16(saddr, gptr) \
    asm volatile("cp.async.cg.shared.global [%0], [%1], 16;" :: "r"(saddr), "l"(gptr))
#define CP_COMMIT()  asm volatile("cp.async.commit_group;" ::: "memory")
#define CP_WAIT_1()  asm volatile("cp.async.wait_group 1;" ::: "memory")
#define CP_WAIT_0()  asm volatile("cp.async.wait_group 0;" ::: "memory")

__device__ __forceinline__ uint32_t smem_u32(const void* p) {
    uint32_t a;
    asm("{ .reg .u64 t; cvta.to.shared.u64 t, %1; cvt.u32.u64 %0, t; }" : "=r"(a) : "l"(p));
    return a;
}

__device__ __forceinline__ void mma_f16(
    float& c0, float& c1, float& c2, float& c3,
    uint32_t a0, uint32_t a1, uint32_t a2, uint32_t a3,
    uint32_t b0, uint32_t b1)
{
    asm volatile(
        "mma.sync.aligned.m16n8k16.row.col.f32.f16.f16.f32 "
        "{%0,%1,%2,%3}, {%4,%5,%6,%7}, {%8,%9}, {%0,%1,%2,%3};"
        : "+f"(c0), "+f"(c1), "+f"(c2), "+f"(c3)
        : "r"(a0), "r"(a1), "r"(a2), "r"(a3), "r"(b0), "r"(b1));
}

#define LDSM_X4(r0, r1, r2, r3, addr) \
    asm volatile("ldmatrix.sync.aligned.m8n8.x4.shared.b16 {%0,%1,%2,%3}, [%4];" \
                 : "=r"(r0), "=r"(r1), "=r"(r2), "=r"(r3) : "r"(addr))

__device__ __forceinline__ uint32_t packh2(float lo, float hi) {
    uint32_t u;
    asm("cvt.rn.f16x2.f32 %0, %1, %2;" : "=r"(u) : "f"(hi), "f"(lo));
    return u;
}

// ---------------------------------------------------------------------------
// TN fp16 tensor-core GEMM (bit-correct core unchanged; bias gains a per-z
// stride so one launch can serve q/k/v with distinct biases)
// ---------------------------------------------------------------------------
#define BKH 64
#define ROWW 36
#define OPW  (128 * ROWW)
#define STW  (2 * OPW)
#define HG_SMEM (2 * STW * 4)       // 73728 bytes

__global__ void __launch_bounds__(256)
hgemm(const __half* __restrict__ A, const __half* __restrict__ B,
      void* __restrict__ Cv, const float* __restrict__ bias,
      int K, int lda, int ldb, int ldc,
      int batch_div,
      long long sAo, long long sAi,
      long long sBo, long long sBi,
      long long sCo, long long sCi,
      long long sBias,
      float alpha, int relu, int outhalf)
{
    extern __shared__ uint32_t smw[];
    const uint32_t sbase = smem_u32(smw);

    const int z  = blockIdx.z;
    const int zo = z / batch_div;
    const int zi = z - zo * batch_div;
    A += zo * sAo + zi * sAi;
    B += zo * sBo + zi * sBi;
    if (bias) bias += zo * sBias;

    const int tid  = threadIdx.x;
    const int lane = tid & 31;
    const int wrp  = tid >> 5;
    const int m0   = blockIdx.y * 128;
    const int n0   = blockIdx.x * 128;

    const int wm = (wrp & 1) * 64;
    const int wn = (wrp >> 1) * 32;
    const int g  = lane >> 2;
    const int tg = lane & 3;

    const __half* Ab = A + (long long)m0 * lda;
    const __half* Bb = B + (long long)n0 * ldb;

    float acc[4][4][4];
#pragma unroll
    for (int mi = 0; mi < 4; mi++)
#pragma unroll
        for (int ni = 0; ni < 4; ni++)
#pragma unroll
            for (int r = 0; r < 4; r++) acc[mi][ni][r] = 0.f;

    const int l15 = lane & 15;
    const int l7  = lane & 7;
    uint32_t aAddr[4], bAddr[2];
#pragma unroll
    for (int mi = 0; mi < 4; mi++)
        aAddr[mi] = sbase + ((wm + mi * 16 + l15) * ROWW + (lane >> 4) * 4) * 4;
#pragma unroll
    for (int p = 0; p < 2; p++)
        bAddr[p] = sbase + OPW * 4 +
                   ((wn + p * 16 + (lane >> 4) * 8 + l7) * ROWW +
                    ((lane >> 3) & 1) * 4) * 4;

    const int lrow = tid >> 3;
    const int lk8  = tid & 7;

    auto issue = [&](int st, int k0) {
        const uint32_t s0 = sbase + (st * STW) * 4;
#pragma unroll
        for (int i = 0; i < 4; i++) {
            const int row = lrow + i * 32;
            const uint32_t off = (row * ROWW + lk8 * 4) * 4;
            CP_ASYNC16(s0 + off,           Ab + (long long)row * lda + k0 + lk8 * 8);
            CP_ASYNC16(s0 + OPW * 4 + off, Bb + (long long)row * ldb + k0 + lk8 * 8);
        }
        CP_COMMIT();
    };

    const int T = K / BKH;
    issue(0, 0);

    for (int it = 0; it < T; it++) {
        const int st = it & 1;
        if (it + 1 < T) {
            issue(st ^ 1, (it + 1) * BKH);
            CP_WAIT_1();
        } else {
            CP_WAIT_0();
        }
        __syncthreads();

        const uint32_t sOff = (uint32_t)(st * STW) * 4;

#pragma unroll
        for (int ks = 0; ks < 4; ks++) {
            const uint32_t ko = sOff + ks * 32;
            uint32_t a[4][4];
#pragma unroll
            for (int mi = 0; mi < 4; mi++)
                LDSM_X4(a[mi][0], a[mi][1], a[mi][2], a[mi][3], aAddr[mi] + ko);
            uint32_t b[4][2];
#pragma unroll
            for (int p = 0; p < 2; p++)
                LDSM_X4(b[2 * p][0], b[2 * p][1], b[2 * p + 1][0], b[2 * p + 1][1],
                        bAddr[p] + ko);
#pragma unroll
            for (int mi = 0; mi < 4; mi++)
#pragma unroll
                for (int ni = 0; ni < 4; ni++)
                    mma_f16(acc[mi][ni][0], acc[mi][ni][1],
                            acc[mi][ni][2], acc[mi][ni][3],
                            a[mi][0], a[mi][1], a[mi][2], a[mi][3],
                            b[ni][0], b[ni][1]);
        }
        __syncthreads();
    }

    float*  Cf = (float*)Cv  + zo * sCo + zi * sCi;
    __half* Ch = (__half*)Cv + zo * sCo + zi * sCi;
#pragma unroll
    for (int mi = 0; mi < 4; mi++) {
        const int r0 = m0 + wm + mi * 16 + g;
#pragma unroll
        for (int ni = 0; ni < 4; ni++) {
            const int col = n0 + wn + ni * 8 + tg * 2;
            float v0 = acc[mi][ni][0], v1 = acc[mi][ni][1];
            float v2 = acc[mi][ni][2], v3 = acc[mi][ni][3];
            if (bias) {
                const float b0 = bias[col], b1 = bias[col + 1];
                v0 += b0; v1 += b1; v2 += b0; v3 += b1;
            }
            v0 *= alpha; v1 *= alpha; v2 *= alpha; v3 *= alpha;
            if (relu) {
                v0 = fmaxf(v0, 0.f); v1 = fmaxf(v1, 0.f);
                v2 = fmaxf(v2, 0.f); v3 = fmaxf(v3, 0.f);
            }
            if (outhalf) {
                *(__half2*)(Ch + (long long)r0 * ldc + col) =
                    __floats2half2_rn(v0, v1);
                *(__half2*)(Ch + (long long)(r0 + 8) * ldc + col) =
                    __floats2half2_rn(v2, v3);
            } else {
                *(float2*)(Cf + (long long)r0 * ldc + col)       = make_float2(v0, v1);
                *(float2*)(Cf + (long long)(r0 + 8) * ldc + col) = make_float2(v2, v3);
            }
        }
    }
}

// ---------------------------------------------------------------------------
// Fused flash attention — R11 VERBATIM (natural-base softmax, unconditional
// rescale). q pre-scaled by 1/sqrt(KD) (folded into weights, bit-exact).
// q,k [b,s,h,e]; vt [bh,e,s].
// ---------------------------------------------------------------------------
#define QROWB 528
#define VROWB 144
#define QBYT  (128 * QROWB)
#define KBYT  (64 * QROWB)
#define VBYT  (256 * VROWB)
#define STBYT (KBYT + VBYT)
#define FA_SMEM (QBYT + 2 * STBYT)   // 208896

__global__ void __launch_bounds__(256, 1)
fattn(const __half* __restrict__ q, const __half* __restrict__ k,
      const __half* __restrict__ vt, __half* __restrict__ o)
{
    extern __shared__ char fsm[];
    const uint32_t sb = smem_u32(fsm);

    const int tid = threadIdx.x, lane = tid & 31, w = tid >> 5;
    const int g = lane >> 2, tg = lane & 3;
    const int l15 = lane & 15, l7 = lane & 7;
    const int qt = blockIdx.x, bh = blockIdx.y;
    const int b = bh >> 3, h = bh & 7;
    const long long tokQ = (long long)b * SS + qt * 128;

    // ---- load Q tile (128 x 256 halves), once ----
#pragma unroll
    for (int i = 0; i < 16; i++) {
        const int c = tid + i * 256, row = c >> 5, col = c & 31;
        CP_ASYNC16(sb + row * QROWB + col * 16,
                   q + ((tokQ + row) * HH + h) * KDD + col * 8);
    }
    CP_COMMIT();

    auto loadKV = [&](int st, int kt) {
        const uint32_t kb = sb + QBYT + st * STBYT;
        const uint32_t vb = kb + KBYT;
#pragma unroll
        for (int i = 0; i < 8; i++) {
            const int c = tid + i * 256, row = c >> 5, col = c & 31;
            CP_ASYNC16(kb + row * QROWB + col * 16,
                       k + (((long long)b * SS + kt * 64 + row) * HH + h) * KDD + col * 8);
        }
#pragma unroll
        for (int i = 0; i < 8; i++) {
            const int c = tid + i * 256, d = c >> 3, kc = c & 7;
            CP_ASYNC16(vb + d * VROWB + kc * 16,
                       vt + ((long long)bh * KDD + d) * SS + kt * 64 + kc * 8);
        }
        CP_COMMIT();
    };

    loadKV(0, 0);

    float acc[32][4];
#pragma unroll
    for (int nd = 0; nd < 32; nd++)
#pragma unroll
        for (int r = 0; r < 4; r++) acc[nd][r] = 0.f;
    float m0 = -1e30f, m1 = -1e30f, l0 = 0.f, l1 = 0.f;

    const uint32_t qa = sb + (w * 16 + l15) * QROWB + (lane >> 4) * 16;

    for (int kt = 0; kt < 32; kt++) {
        const int st = kt & 1;
        if (kt + 1 < 32) { loadKV(st ^ 1, kt + 1); CP_WAIT_1(); }
        else             { CP_WAIT_0(); }
        __syncthreads();

        const uint32_t kb = sb + QBYT + st * STBYT;
        const uint32_t vb = kb + KBYT;
        const uint32_t ka = kb + ((lane >> 4) * 8 + l7) * QROWB + ((lane >> 3) & 1) * 16;
        const uint32_t va = vb + ((lane >> 4) * 8 + l7) * VROWB + ((lane >> 3) & 1) * 16;

        // ---- S = Qw (16 x 256) @ Ktile^T (64 x 256) ----
        float s[8][4];
#pragma unroll
        for (int ni = 0; ni < 8; ni++)
#pragma unroll
            for (int r = 0; r < 4; r++) s[ni][r] = 0.f;

#pragma unroll
        for (int kk = 0; kk < 16; kk++) {
            uint32_t a0, a1, a2, a3;
            LDSM_X4(a0, a1, a2, a3, qa + kk * 32);
#pragma unroll
            for (int p = 0; p < 4; p++) {
                uint32_t b0, b1, b2, b3;
                LDSM_X4(b0, b1, b2, b3, ka + p * 16 * QROWB + kk * 32);
                mma_f16(s[2 * p][0], s[2 * p][1], s[2 * p][2], s[2 * p][3],
                        a0, a1, a2, a3, b0, b1);
                mma_f16(s[2 * p + 1][0], s[2 * p + 1][1], s[2 * p + 1][2], s[2 * p + 1][3],
                        a0, a1, a2, a3, b2, b3);
            }
        }

        // ---- online softmax update (rows g and g+8) ----
        float r0 = -1e30f, r1 = -1e30f;
#pragma unroll
        for (int ni = 0; ni < 8; ni++) {
            r0 = fmaxf(r0, fmaxf(s[ni][0], s[ni][1]));
            r1 = fmaxf(r1, fmaxf(s[ni][2], s[ni][3]));
        }
        r0 = fmaxf(r0, __shfl_xor_sync(0xffffffffu, r0, 1));
        r0 = fmaxf(r0, __shfl_xor_sync(0xffffffffu, r0, 2));
        r1 = fmaxf(r1, __shfl_xor_sync(0xffffffffu, r1, 1));
        r1 = fmaxf(r1, __shfl_xor_sync(0xffffffffu, r1, 2));
        const float mn0 = fmaxf(m0, r0), mn1 = fmaxf(m1, r1);
        const float sc0 = __expf(m0 - mn0), sc1 = __expf(m1 - mn1);

        uint32_t afr[4][4];
        float ps0 = 0.f, ps1 = 0.f;
#pragma unroll
        for (int kk = 0; kk < 4; kk++) {
            const float p00 = __expf(s[2 * kk][0] - mn0);
            const float p01 = __expf(s[2 * kk][1] - mn0);
            const float p10 = __expf(s[2 * kk][2] - mn1);
            const float p11 = __expf(s[2 * kk][3] - mn1);
            const float p20 = __expf(s[2 * kk + 1][0] - mn0);
            const float p21 = __expf(s[2 * kk + 1][1] - mn0);
            const float p30 = __expf(s[2 * kk + 1][2] - mn1);
            const float p31 = __expf(s[2 * kk + 1][3] - mn1);
            ps0 += p00 + p01 + p20 + p21;
            ps1 += p10 + p11 + p30 + p31;
            afr[kk][0] = packh2(p00, p01);
            afr[kk][1] = packh2(p10, p11);
            afr[kk][2] = packh2(p20, p21);
            afr[kk][3] = packh2(p30, p31);
        }
        l0 = l0 * sc0 + ps0;
        l1 = l1 * sc1 + ps1;
#pragma unroll
        for (int nd = 0; nd < 32; nd++) {
            acc[nd][0] *= sc0; acc[nd][1] *= sc0;
            acc[nd][2] *= sc1; acc[nd][3] *= sc1;
        }
        m0 = mn0; m1 = mn1;

        // ---- O += P (16 x 64) @ Vtile (64 x 256) ----
#pragma unroll
        for (int kk = 0; kk < 4; kk++) {
#pragma unroll
            for (int p = 0; p < 16; p++) {
                uint32_t b0, b1, b2, b3;
                LDSM_X4(b0, b1, b2, b3, va + p * 16 * VROWB + kk * 32);
                mma_f16(acc[2 * p][0], acc[2 * p][1], acc[2 * p][2], acc[2 * p][3],
                        afr[kk][0], afr[kk][1], afr[kk][2], afr[kk][3], b0, b1);
                mma_f16(acc[2 * p + 1][0], acc[2 * p + 1][1],
                        acc[2 * p + 1][2], acc[2 * p + 1][3],
                        afr[kk][0], afr[kk][1], afr[kk][2], afr[kk][3], b2, b3);
            }
        }
        __syncthreads();
    }

    // ---- finalize: divide by l, store fp16 [b,s,h,e] ----
    l0 += __shfl_xor_sync(0xffffffffu, l0, 1);
    l0 += __shfl_xor_sync(0xffffffffu, l0, 2);
    l1 += __shfl_xor_sync(0xffffffffu, l1, 1);
    l1 += __shfl_xor_sync(0xffffffffu, l1, 2);
    const float inv0 = 1.f / l0, inv1 = 1.f / l1;

    __half* o0 = o + ((tokQ + w * 16 + g) * HH + h) * KDD;
    __half* o1 = o + ((tokQ + w * 16 + g + 8) * HH + h) * KDD;
#pragma unroll
    for (int nd = 0; nd < 32; nd++) {
        const int col = nd * 8 + tg * 2;
        *(__half2*)(o0 + col) = __floats2half2_rn(acc[nd][0] * inv0, acc[nd][1] * inv0);
        *(__half2*)(o1 + col) = __floats2half2_rn(acc[nd][2] * inv1, acc[nd][3] * inv1);
    }
}

// ---------------------------------------------------------------------------
// Prep kernels
// ---------------------------------------------------------------------------
__global__ void __launch_bounds__(256)
conv_h(const float* __restrict__ src, __half* __restrict__ dst, int n)
{
    int i = blockIdx.x * 256 + threadIdx.x;
    if (i < n) dst[i] = __float2half_rn(src[i]);
}

// Pack biases: [bq*2^-4 | bk | bv] -> g_b3 (power-of-2 scale is bit-exact)
__global__ void __launch_bounds__(256)
pack_b3(const float* __restrict__ bq, const float* __restrict__ bk,
        const float* __restrict__ bv, float* __restrict__ dst)
{
    const int i = blockIdx.x * 256 + threadIdx.x;   // 0..6143
    float v;
    if (i < HKD)           v = bq[i] * 0.0625f;
    else if (i < 2 * HKD)  v = bk[i - HKD];
    else                   v = bv[i - 2 * HKD];
    dst[i] = v;
}

// Batched weight transpose: all six [K,N] fp32 -> [N,K] fp16 in ONE launch.
// Wq segment is scaled by 2^-4 (exact), so the QKV GEMM runs with alpha=1.
__global__ void __launch_bounds__(256)
convT_all(const float* __restrict__ Wq, const float* __restrict__ Wk,
          const float* __restrict__ Wv, const float* __restrict__ Wo,
          const float* __restrict__ W1, const float* __restrict__ W2,
          __half* __restrict__ wqkv, __half* __restrict__ wo,
          __half* __restrict__ w1, __half* __restrict__ w2)
{
    const int bid = blockIdx.x;
    const float* src; __half* dst; int Kd, Nd, t; float sc = 1.f;
    if (bid < 512)       { src = Wq; dst = wqkv;                    Kd = DD;  Nd = HKD; t = bid;        sc = 0.0625f; }
    else if (bid < 1024) { src = Wk; dst = wqkv + (long long)HKD * DD;     Kd = DD;  Nd = HKD; t = bid - 512; }
    else if (bid < 1536) { src = Wv; dst = wqkv + (long long)2 * HKD * DD; Kd = DD;  Nd = HKD; t = bid - 1024; }
    else if (bid < 2048) { src = Wo; dst = wo; Kd = HKD; Nd = DD;  t = bid - 1536; }
    else if (bid < 2176) { src = W1; dst = w1; Kd = DD;  Nd = FFD; t = bid - 2048; }
    else                 { src = W2; dst = w2; Kd = FFD; Nd = DD;  t = bid - 2176; }
    const int nK = Kd / 32;
    const int k0 = (t % nK) * 32, n0 = (t / nK) * 32;

    __shared__ float tt[32][33];
    const int tx = threadIdx.x & 31, ty = threadIdx.x >> 5;
#pragma unroll
    for (int i = ty; i < 32; i += 8)
        tt[i][tx] = src[(long long)(k0 + i) * Nd + n0 + tx];
    __syncthreads();
#pragma unroll
    for (int i = ty; i < 32; i += 8)
        dst[(long long)(n0 + i) * Kd + k0 + tx] = __float2half_rn(tt[tx][i] * sc);
}

// v[b,s,h,e] fp16 -> vt[bh,e,s] fp16 (unchanged)
__global__ void __launch_bounds__(256)
vtrans_h(const __half* __restrict__ v, __half* __restrict__ vt)
{
    __shared__ __half t[32][33];
    const int tx = threadIdx.x & 31, ty = threadIdx.x >> 5;
    const int bh = blockIdx.z, b = bh >> 3, h = bh & 7;
    const int s0 = blockIdx.x * 32, e0 = blockIdx.y * 32;
#pragma unroll
    for (int i = ty; i < 32; i += 8)
        t[i][tx] = v[((long long)(b * SS + s0 + i) * HH + h) * KDD + e0 + tx];
    __syncthreads();
#pragma unroll
    for (int i = ty; i < 32; i += 8)
        vt[((long long)bh * KDD + e0 + i) * SS + s0 + tx] = t[tx][i];
}

// ---------------------------------------------------------------------------
// LayerNorm (+ residual) — unchanged
// ---------------------------------------------------------------------------
__global__ void __launch_bounds__(256)
ln_kernel(const float* __restrict__ a, const float* __restrict__ r,
          const float* __restrict__ g, const float* __restrict__ b,
          float* __restrict__ out, __half* __restrict__ out16, int add_before)
{
    const int t = threadIdx.x;
    const long long base = (long long)blockIdx.x * DD;
    const float av = a[base + t];
    const float rv = r[base + t];
    const float val = add_before ? (av + rv) : av;

    __shared__ float sh[256];
    sh[t] = val; __syncthreads();
    for (int st = 128; st; st >>= 1) {
        if (t < st) sh[t] += sh[t + st];
        __syncthreads();
    }
    const float mean = sh[0] * (1.f / 256.f);
    __syncthreads();

    const float d = val - mean;
    sh[t] = d * d; __syncthreads();
    for (int st = 128; st; st >>= 1) {
        if (t < st) sh[t] += sh[t + st];
        __syncthreads();
    }
    const float var = sh[0] * (1.f / 256.f);

    const float y = d * rsqrtf(var + 1e-3f) * g[t] + b[t];
    const float o = add_before ? y : (y + rv);
    out[base + t] = o;
    if (out16) out16[base + t] = __float2half_rn(o);
}

// ---------------------------------------------------------------------------
// Launch
// ---------------------------------------------------------------------------
extern "C" void kernel_launch(void* const* d_in, const int* in_sizes, int n_in,
                              void* d_out, int out_size)
{
    const float* x   = (const float*)d_in[0];
    const float* Wq  = (const float*)d_in[1];
    const float* bq  = (const float*)d_in[2];
    const float* Wk  = (const float*)d_in[3];
    const float* bk  = (const float*)d_in[4];
    const float* Wv  = (const float*)d_in[5];
    const float* bv  = (const float*)d_in[6];
    const float* Wo  = (const float*)d_in[7];
    const float* bo  = (const float*)d_in[8];
    const float* g1  = (const float*)d_in[9];
    const float* be1 = (const float*)d_in[10];
    const float* W1  = (const float*)d_in[11];
    const float* bb1 = (const float*)d_in[12];
    const float* W2  = (const float*)d_in[13];
    const float* bb2 = (const float*)d_in[14];
    const float* g2  = (const float*)d_in[15];
    const float* be2 = (const float*)d_in[16];
    float* out = (float*)d_out;

    __half *qkv3, *vt16, *at16, *z16, *h16;
    __half *x16, *wqkv3, *wo16, *w116, *w216;
    float *b3, *ao, *zz, *ff;
    cudaGetSymbolAddress((void**)&qkv3,  g_qkv3);
    cudaGetSymbolAddress((void**)&vt16,  g_vt16);
    cudaGetSymbolAddress((void**)&at16,  g_at16);
    cudaGetSymbolAddress((void**)&z16,   g_z16);
    cudaGetSymbolAddress((void**)&h16,   g_h16);
    cudaGetSymbolAddress((void**)&x16,   g_x16);
    cudaGetSymbolAddress((void**)&wqkv3, g_wqkv3);
    cudaGetSymbolAddress((void**)&b3,    g_b3);
    cudaGetSymbolAddress((void**)&wo16,  g_wo16);
    cudaGetSymbolAddress((void**)&w116,  g_w116);
    cudaGetSymbolAddress((void**)&w216,  g_w216);
    cudaGetSymbolAddress((void**)&ao,    g_ao);
    cudaGetSymbolAddress((void**)&zz,    g_z);
    cudaGetSymbolAddress((void**)&ff,    g_f);

    __half* q16 = qkv3;
    __half* k16 = qkv3 + (long long)MTOK * HKD;
    __half* v16 = qkv3 + (long long)2 * MTOK * HKD;

    cudaFuncSetAttribute(hgemm, cudaFuncAttributeMaxDynamicSharedMemorySize, HG_SMEM);
    cudaFuncSetAttribute(fattn, cudaFuncAttributeMaxDynamicSharedMemorySize, FA_SMEM);

    const dim3 blk(256);

    // ---- prep: 3 launches ---------------------------------------------------
    conv_h<<<(MTOK * DD) / 256, blk>>>(x, x16, MTOK * DD);
    pack_b3<<<(3 * HKD) / 256, blk>>>(bq, bk, bv, b3);
    convT_all<<<2304, blk>>>(Wq, Wk, Wv, Wo, W1, W2,
                             wqkv3, wo16, w116, w216);

    // ---- Q/K/V projections: ONE batched launch (z selects q/k/v) ------------
    {
        dim3 grid(HKD / 128, MTOK / 128, 3);
        hgemm<<<grid, blk, HG_SMEM>>>(x16, wqkv3, qkv3, b3, DD, DD, DD, HKD,
                                      1,
                                      0, 0,
                                      (long long)HKD * DD, 0,
                                      (long long)MTOK * HKD, 0,
                                      (long long)HKD,
                                      1.f, 0, 1);
    }

    // ---- vt[bh,e,s] ---------------------------------------------------------
    vtrans_h<<<dim3(SS / 32, KDD / 32, BH), blk>>>(v16, vt16);

    // ---- fused attention ----------------------------------------------------
    fattn<<<dim3(SS / 128, BH), blk, FA_SMEM>>>(q16, k16, vt16, at16);

    // ---- output projection --------------------------------------------------
    {
        dim3 grid(DD / 128, MTOK / 128, 1);
        hgemm<<<grid, blk, HG_SMEM>>>(at16, wo16, ao, bo, HKD, HKD, HKD, DD,
                                      1, 0, 0, 0, 0, 0, 0, 0,
                                      1.f, 0, 0);
    }

    // ---- z = LN(attn_out) + x ----------------------------------------------
    ln_kernel<<<MTOK, blk>>>(ao, x, g1, be1, zz, z16, 0);

    // ---- FFN ----------------------------------------------------------------
    {
        dim3 grid(FFD / 128, MTOK / 128, 1);
        hgemm<<<grid, blk, HG_SMEM>>>(z16, w116, h16, bb1, DD, DD, DD, FFD,
                                      1, 0, 0, 0, 0, 0, 0, 0,
                                      1.f, 1, 1);
    }
    {
        dim3 grid(DD / 128, MTOK / 128, 1);
        hgemm<<<grid, blk, HG_SMEM>>>(h16, w216, ff, bb2, FFD, FFD, FFD, DD,
                                      1, 0, 0, 0, 0, 0, 0, 0,
                                      1.f, 0, 0);
    }

    // ---- out = LN(f + z) ----------------------------------------------------
    ln_kernel<<<MTOK, blk>>>(ff, zz, g2, be2, out, nullptr, 1);
}